// round 7
// baseline (speedup 1.0000x reference)
#include <cuda_runtime.h>

// UnifiedQuantumRegressor — fused 3-layer MLP + reduction.
// f32x2 row-pair engine (R6) + persistent tile-stealing for occupancy/balance.
//
// Algebra (verified since R1, rel_err 4e-7): all edge weights are 1.0 ->
// mean_w == 1.0 exactly -> attn == q_out; the O(N^2) fidelity stage is dead.
// out = (sum_i tanh(relu(relu(s_i@W1+b1)@W2+b2)@Wq+bq)) @ Wh + bh
//
// f32x2 halves = ROW PAIRS: activations in smem as float2 (row2p, row2p+1)
// keyed by k. One broadcast LDS feeds pairs; one contiguous-lane LDG.128
// feeds 4 weight cols. Per warp-k: 8 FFMA2 (16 cyc FMA) vs 5 L1 wavefronts.
//
// Tiles of 16 rows (512 tiles). 444 CTAs steal tiles via an atomic ticket;
// per-tile partials land in g_partials[tile] -> deterministic final sum.

#define NTHREADS 256
#define TM       16
#define NTILES   512          // 8192 / TM
#define NCTA     444          // 3 * 148
#define PITCH    10           // float2 per k-row: 8 pairs + 2 pad (16B align)

__device__ float        g_partials[NTILES];
__device__ unsigned int g_ticket;   // tile dispenser
__device__ unsigned int g_count;    // done-CTA counter

typedef unsigned long long ull;

static __device__ __forceinline__ ull packf2(float lo, float hi) {
    ull r; asm("mov.b64 %0, {%1, %2};" : "=l"(r) : "f"(lo), "f"(hi)); return r;
}
static __device__ __forceinline__ void ffma2(ull& acc, ull a, ull b) {
    asm("fma.rn.f32x2 %0, %1, %2, %0;" : "+l"(acc) : "l"(a), "l"(b));
}
static __device__ __forceinline__ float2 unpackf2(ull v) {
    float2 f; asm("mov.b64 {%0, %1}, %2;" : "=f"(f.x), "=f"(f.y) : "l"(v)); return f;
}

__global__ __launch_bounds__(NTHREADS) void fused_mlp_kernel(
    const float* __restrict__ S,   // [8192,512]
    const float* __restrict__ W1,  // [512,256]
    const float* __restrict__ b1,  // [256]
    const float* __restrict__ W2,  // [256,256]
    const float* __restrict__ b2,  // [256]
    const float* __restrict__ Wq,  // [256,64]
    const float* __restrict__ bq,  // [64]
    const float* __restrict__ Wh,  // [64]
    const float* __restrict__ bh,  // [1]
    float* __restrict__ out)
{
    __shared__ float2 sE1[256][PITCH];   // 20480 B  enc1, pair-transposed
    __shared__ float2 sE2[256][PITCH];   // 20480 B  enc2; first half doubles as sS
    __shared__ float  sRed[8];
    __shared__ int    sTile;
    __shared__ int    sIsLast;
    float2 (*sS)[PITCH] = sE2;           // S chunk [128 k][8 pairs], dead before sE2 born

    const int tid  = threadIdx.x;
    const int w    = tid >> 5;
    const int lane = tid & 31;

    // compute-tile mapping (stages 1 & 2): 2 pairs x 4 cols per thread
    const int rg = tid >> 6;          // 0..3 -> pairs p0, p0+1
    const int cg = tid & 63;          // cols c0 .. c0+3
    const int p0 = rg * 2;
    const int c0 = cg * 4;

    // chunk-loader mapping: pair pr (0..7), k-quad (k0 = 4*kq, kq 0..31)
    const int pr = tid & 7;
    const int k0 = (tid >> 3) * 4;

    while (true) {
        // ---- steal a tile ----
        if (tid == 0) {
            unsigned int t = atomicAdd(&g_ticket, 1u);
            sTile = (t < NTILES) ? (int)t : -1;
        }
        __syncthreads();
        const int tile = sTile;
        __syncthreads();                 // protect sTile before next overwrite
        if (tile < 0) break;
        const int row0 = tile * TM;

        ull acc[2][4];                   // [pair][col]

        // ============ stage 1: enc1 = relu(S @ W1 + b1) ============
        #pragma unroll
        for (int p = 0; p < 2; ++p)
            #pragma unroll
            for (int c = 0; c < 4; ++c) acc[p][c] = 0ull;

        #pragma unroll 1
        for (int ch = 0; ch < 4; ++ch) {
            // load S chunk [16 rows x 128 k] into pair-transposed sS
            {
                const float* rA = S + (size_t)(row0 + 2 * pr) * 512 + ch * 128 + k0;
                const float4 a0 = *(const float4*)rA;
                const float4 b0 = *(const float4*)(rA + 512);
                sS[k0 + 0][pr] = make_float2(a0.x, b0.x);
                sS[k0 + 1][pr] = make_float2(a0.y, b0.y);
                sS[k0 + 2][pr] = make_float2(a0.z, b0.z);
                sS[k0 + 3][pr] = make_float2(a0.w, b0.w);
            }
            __syncthreads();

            const float* Wp = W1 + (size_t)(ch * 128) * 256;
            #pragma unroll 4
            for (int k = 0; k < 128; ++k) {
                const float4 wv = *(const float4*)(Wp + k * 256 + c0);  // LDG.128
                const ull wd0 = packf2(wv.x, wv.x);
                const ull wd1 = packf2(wv.y, wv.y);
                const ull wd2 = packf2(wv.z, wv.z);
                const ull wd3 = packf2(wv.w, wv.w);
                const ulonglong2 sA = *(const ulonglong2*)&sS[k][p0];    // 2 pairs, bcast
                ffma2(acc[0][0], sA.x, wd0); ffma2(acc[0][1], sA.x, wd1);
                ffma2(acc[0][2], sA.x, wd2); ffma2(acc[0][3], sA.x, wd3);
                ffma2(acc[1][0], sA.y, wd0); ffma2(acc[1][1], sA.y, wd1);
                ffma2(acc[1][2], sA.y, wd2); ffma2(acc[1][3], sA.y, wd3);
            }
            __syncthreads();             // sS consumed before next chunk overwrites
        }

        // epilogue 1: bias + relu -> sE1[col][pair]
        {
            const float4 bb = *(const float4*)(b1 + c0);
            const float bc[4] = {bb.x, bb.y, bb.z, bb.w};
            #pragma unroll
            for (int c = 0; c < 4; ++c)
                #pragma unroll
                for (int p = 0; p < 2; ++p) {
                    float2 v = unpackf2(acc[p][c]);
                    sE1[c0 + c][p0 + p] =
                        make_float2(fmaxf(v.x + bc[c], 0.f), fmaxf(v.y + bc[c], 0.f));
                }
        }
        __syncthreads();

        // ============ stage 2: enc2 = relu(enc1 @ W2 + b2) ============
        #pragma unroll
        for (int p = 0; p < 2; ++p)
            #pragma unroll
            for (int c = 0; c < 4; ++c) acc[p][c] = 0ull;

        #pragma unroll 4
        for (int k = 0; k < 256; ++k) {
            const float4 wv = *(const float4*)(W2 + k * 256 + c0);
            const ull wd0 = packf2(wv.x, wv.x);
            const ull wd1 = packf2(wv.y, wv.y);
            const ull wd2 = packf2(wv.z, wv.z);
            const ull wd3 = packf2(wv.w, wv.w);
            const ulonglong2 sA = *(const ulonglong2*)&sE1[k][p0];
            ffma2(acc[0][0], sA.x, wd0); ffma2(acc[0][1], sA.x, wd1);
            ffma2(acc[0][2], sA.x, wd2); ffma2(acc[0][3], sA.x, wd3);
            ffma2(acc[1][0], sA.y, wd0); ffma2(acc[1][1], sA.y, wd1);
            ffma2(acc[1][2], sA.y, wd2); ffma2(acc[1][3], sA.y, wd3);
        }
        __syncthreads();                 // sE2 region (sS alias) free now

        // epilogue 2: bias + relu -> sE2[col][pair]
        {
            const float4 bb = *(const float4*)(b2 + c0);
            const float bc[4] = {bb.x, bb.y, bb.z, bb.w};
            #pragma unroll
            for (int c = 0; c < 4; ++c)
                #pragma unroll
                for (int p = 0; p < 2; ++p) {
                    float2 v = unpackf2(acc[p][c]);
                    sE2[c0 + c][p0 + p] =
                        make_float2(fmaxf(v.x + bc[c], 0.f), fmaxf(v.y + bc[c], 0.f));
                }
        }
        __syncthreads();

        // ======= stage 3: q = tanh(enc2 @ Wq + bq);  part = q . Wh =======
        float part;
        {
            const int rg3 = tid >> 5;     // pair 0..7
            const int c3  = (tid & 31) * 2;

            ull a3[2] = {0ull, 0ull};
            #pragma unroll 4
            for (int k = 0; k < 256; ++k) {
                const float2 wv = *(const float2*)(Wq + k * 64 + c3);
                const ull sp = *(const ull*)&sE2[k][rg3];   // LDS.64 broadcast
                ffma2(a3[0], sp, packf2(wv.x, wv.x));
                ffma2(a3[1], sp, packf2(wv.y, wv.y));
            }
            const float2 bq2 = *(const float2*)(bq + c3);
            const float2 wh2 = *(const float2*)(Wh + c3);
            const float2 v0 = unpackf2(a3[0]);
            const float2 v1 = unpackf2(a3[1]);
            part = (tanhf(v0.x + bq2.x) + tanhf(v0.y + bq2.x)) * wh2.x
                 + (tanhf(v1.x + bq2.y) + tanhf(v1.y + bq2.y)) * wh2.y;
        }

        // ---- block reduce (fixed order) -> per-tile partial ----
        #pragma unroll
        for (int o = 16; o > 0; o >>= 1)
            part += __shfl_down_sync(0xffffffffu, part, o);
        if (lane == 0) sRed[w] = part;
        __syncthreads();
        if (tid == 0) {
            float tot = 0.f;
            #pragma unroll
            for (int i = 0; i < 8; ++i) tot += sRed[i];
            g_partials[tile] = tot;
        }
        __syncthreads();                 // sRed/sE reusable next iteration
    }

    // ---- CTA done: arrive; last CTA does deterministic final reduction ----
    if (tid == 0) {
        __threadfence();
        unsigned int c = atomicAdd(&g_count, 1u);
        sIsLast = (c == NCTA - 1u);
    }
    __syncthreads();

    if (sIsLast) {
        volatile float* gp = g_partials;
        float v = gp[tid] + gp[tid + 256];     // 512 partials, fixed order
        #pragma unroll
        for (int o = 16; o > 0; o >>= 1)
            v += __shfl_down_sync(0xffffffffu, v, o);
        if (lane == 0) sRed[w] = v;
        __syncthreads();
        if (tid == 0) {
            float t = 0.f;
            #pragma unroll
            for (int i = 0; i < 8; ++i) t += sRed[i];
            out[0] = t + bh[0];
            g_ticket = 0;                      // self-reset for graph replay
            g_count  = 0;
        }
    }
}

extern "C" void kernel_launch(void* const* d_in, const int* in_sizes, int n_in,
                              void* d_out, int out_size)
{
    const float* S  = (const float*)d_in[0];
    const float* W1 = (const float*)d_in[1];
    const float* b1 = (const float*)d_in[2];
    const float* W2 = (const float*)d_in[3];
    const float* b2 = (const float*)d_in[4];
    const float* Wq = (const float*)d_in[5];
    const float* bq = (const float*)d_in[6];
    const float* Wh = (const float*)d_in[7];
    const float* bh = (const float*)d_in[8];
    float* out = (float*)d_out;

    fused_mlp_kernel<<<NCTA, NTHREADS>>>(S, W1, b1, W2, b2, Wq, bq, Wh, bh, out);
}

// round 8
// speedup vs baseline: 2.4087x; 2.4087x over previous
#include <cuda_runtime.h>
#include <cuda_bf16.h>

// UnifiedQuantumRegressor — hybrid tensor/FFMA2 fused MLP + reduction.
//
// Algebra (verified since R1): all edge weights are 1.0 -> mean_w == 1.0
// exactly -> attn == q_out; the O(N^2) fidelity stage is dead.
// out = (sum_i tanh(relu(relu(s_i@W1+b1)@W2+b2)@Wq+bq)) @ Wh + bh
//
// Stage 1 (8192x512x256, 61% of MACs): mma.sync m16n8k16 bf16, 3-pass
//   split-compensated (Ahi*Bhi + Ahi*Blo + Alo*Bhi, fp32 accum) -> ~2^-17
//   effective precision. W1 pre-split+packed into B-fragment order by a prep
//   kernel (device scratch); S split on the fly while staging to smem.
// Stages 2+3: the validated R6 f32x2 row-pair FFMA2 engine, unchanged.

#define NTHREADS 256
#define TM       32
#define NBLK     256          // 8192 / 32
#define PITCH    18           // float2 per k-row of sE: 16 pairs + pad

// W1 packed B-fragments: [32 ksteps][32 n8-blocks][32 lanes] {bhi0,bhi1,blo0,blo1}
__device__ uint4        g_W1pack[32 * 32 * 32];     // 512 KB
__device__ float        g_partials[NBLK];
__device__ unsigned int g_count;

typedef unsigned long long ull;

static __device__ __forceinline__ ull packf2(float lo, float hi) {
    ull r; asm("mov.b64 %0, {%1, %2};" : "=l"(r) : "f"(lo), "f"(hi)); return r;
}
static __device__ __forceinline__ void ffma2(ull& acc, ull a, ull b) {
    asm("fma.rn.f32x2 %0, %1, %2, %0;" : "+l"(acc) : "l"(a), "l"(b));
}
static __device__ __forceinline__ float2 unpackf2(ull v) {
    float2 f; asm("mov.b64 {%0, %1}, %2;" : "=f"(f.x), "=f"(f.y) : "l"(v)); return f;
}
// bf16x2 pack: element for lower k index goes in LOW 16 bits (.x)
static __device__ __forceinline__ unsigned pack_bf2(float a, float b) {
    __nv_bfloat162 h; h.x = __float2bfloat16(a); h.y = __float2bfloat16(b);
    return *(unsigned*)&h;
}
static __device__ __forceinline__ float bf_res(float x) {
    return x - __bfloat162float(__float2bfloat16(x));
}
static __device__ __forceinline__ void mma_bf16(float* d,
    unsigned a0, unsigned a1, unsigned a2, unsigned a3,
    unsigned b0, unsigned b1)
{
    asm volatile(
        "mma.sync.aligned.m16n8k16.row.col.f32.bf16.bf16.f32 "
        "{%0,%1,%2,%3}, {%4,%5,%6,%7}, {%8,%9}, {%0,%1,%2,%3};"
        : "+f"(d[0]), "+f"(d[1]), "+f"(d[2]), "+f"(d[3])
        : "r"(a0), "r"(a1), "r"(a2), "r"(a3), "r"(b0), "r"(b1));
}

// ---- prep: split W1 into bf16 hi/lo and pack in B-fragment order ----
__global__ __launch_bounds__(512) void prep_W1_kernel(const float* __restrict__ W1)
{
    int idx = blockIdx.x * blockDim.x + threadIdx.x;     // 0 .. 32767
    if (idx >= 32 * 32 * 32) return;
    const int l  = idx & 31;
    const int nb = (idx >> 5) & 31;
    const int s  = idx >> 10;
    const int g = l >> 2, t = l & 3;
    const int n  = nb * 8 + g;
    const int k0 = s * 16 + 2 * t;
    const float w00 = W1[(k0    ) * 256 + n];
    const float w01 = W1[(k0 + 1) * 256 + n];
    const float w10 = W1[(k0 + 8) * 256 + n];
    const float w11 = W1[(k0 + 9) * 256 + n];
    uint4 v;
    v.x = pack_bf2(w00, w01);                    // bhi0: k lo-half
    v.y = pack_bf2(w10, w11);                    // bhi1: k hi-half
    v.z = pack_bf2(bf_res(w00), bf_res(w01));    // blo0
    v.w = pack_bf2(bf_res(w10), bf_res(w11));    // blo1
    g_W1pack[idx] = v;
}

__global__ __launch_bounds__(NTHREADS) void fused_mlp_kernel(
    const float* __restrict__ S,   // [8192,512]
    const float* __restrict__ b1,  // [256]
    const float* __restrict__ W2,  // [256,256]
    const float* __restrict__ b2,  // [256]
    const float* __restrict__ Wq,  // [256,64]
    const float* __restrict__ bq,  // [64]
    const float* __restrict__ Wh,  // [64]
    const float* __restrict__ bh,  // [1]
    float* __restrict__ out)
{
    extern __shared__ unsigned char dynsm[];
    // region0 [0, 65536):  sAhi [32 s][32 r][4 t] uint2 (32KB) + sAlo (32KB)
    //                      later overlaid by sE2 [256][PITCH] float2 (36KB)
    // region1 [65536, 102400): sE1 [256][PITCH] float2 (36KB)
    uint2* sAhi = (uint2*)dynsm;
    uint2* sAlo = (uint2*)(dynsm + 32768);
    float2 (*sE2)[PITCH] = (float2(*)[PITCH])dynsm;
    float2 (*sE1)[PITCH] = (float2(*)[PITCH])(dynsm + 65536);
    __shared__ float sRed[8];
    __shared__ int   sIsLast;

    const int tid  = threadIdx.x;
    const int w    = tid >> 5;
    const int lane = tid & 31;
    const int row0 = blockIdx.x * TM;

    // ---- stage S tile [32 x 512] into smem, split bf16 hi/lo, frag layout ----
    {
        const int r  = tid >> 3;            // 0..31
        const int s0 = (tid & 7) * 4;       // 4 ksteps per thread
        const float* Srow = S + (size_t)(row0 + r) * 512;
        #pragma unroll
        for (int i = 0; i < 4; ++i) {
            const int s = s0 + i;
            const float4 x0 = *(const float4*)(Srow + s * 16);
            const float4 x1 = *(const float4*)(Srow + s * 16 + 4);
            const float4 x2 = *(const float4*)(Srow + s * 16 + 8);
            const float4 x3 = *(const float4*)(Srow + s * 16 + 12);
            const int base = s * 128 + r * 4;
            sAhi[base + 0] = make_uint2(pack_bf2(x0.x, x0.y), pack_bf2(x2.x, x2.y));
            sAhi[base + 1] = make_uint2(pack_bf2(x0.z, x0.w), pack_bf2(x2.z, x2.w));
            sAhi[base + 2] = make_uint2(pack_bf2(x1.x, x1.y), pack_bf2(x3.x, x3.y));
            sAhi[base + 3] = make_uint2(pack_bf2(x1.z, x1.w), pack_bf2(x3.z, x3.w));
            sAlo[base + 0] = make_uint2(pack_bf2(bf_res(x0.x), bf_res(x0.y)),
                                        pack_bf2(bf_res(x2.x), bf_res(x2.y)));
            sAlo[base + 1] = make_uint2(pack_bf2(bf_res(x0.z), bf_res(x0.w)),
                                        pack_bf2(bf_res(x2.z), bf_res(x2.w)));
            sAlo[base + 2] = make_uint2(pack_bf2(bf_res(x1.x), bf_res(x1.y)),
                                        pack_bf2(bf_res(x3.x), bf_res(x3.y)));
            sAlo[base + 3] = make_uint2(pack_bf2(bf_res(x1.z), bf_res(x1.w)),
                                        pack_bf2(bf_res(x3.z), bf_res(x3.w)));
        }
    }
    __syncthreads();

    // ================= stage 1: enc1 = relu(S @ W1 + b1) — tensor =================
    {
        const int mt = w >> 2;              // m-tile 0/1 (rows mt*16 .. +15)
        const int q  = w & 3;               // n-quarter (cols q*64 .. +63)
        const int g  = lane >> 2, t = lane & 3;
        const int rA0 = (mt * 16 + g) * 4 + t;   // conflict-free: lane-distinct
        const int rA1 = rA0 + 32;                // row +8

        float acc[8][4];
        #pragma unroll
        for (int nb = 0; nb < 8; ++nb)
            #pragma unroll
            for (int j = 0; j < 4; ++j) acc[nb][j] = 0.f;

        #pragma unroll 1
        for (int s = 0; s < 32; ++s) {
            const uint2 Ah0 = sAhi[s * 128 + rA0];   // .x=a0, .y=a2
            const uint2 Ah1 = sAhi[s * 128 + rA1];   // .x=a1, .y=a3
            const uint2 Al0 = sAlo[s * 128 + rA0];
            const uint2 Al1 = sAlo[s * 128 + rA1];
            const uint4* bp = g_W1pack + ((s * 32 + q * 8) * 32 + lane);
            #pragma unroll
            for (int nb = 0; nb < 8; ++nb) {
                const uint4 B = bp[nb * 32];         // coalesced LDG.128
                mma_bf16(acc[nb], Ah0.x, Ah1.x, Ah0.y, Ah1.y, B.x, B.y);  // hi*hi
                mma_bf16(acc[nb], Ah0.x, Ah1.x, Ah0.y, Ah1.y, B.z, B.w);  // hi*lo
                mma_bf16(acc[nb], Al0.x, Al1.x, Al0.y, Al1.y, B.x, B.y);  // lo*hi
            }
        }
        __syncthreads();    // all sA reads done (also before sE1 pub below)

        // epilogue 1: bias + relu -> sE1[col][pair] (R6 stage-2 input layout)
        const int mlo = mt * 16 + g;
        const int mhi = mlo + 8;
        const int plo2 = (mlo >> 1) * 2 + (mlo & 1);   // float index within sE1 row
        const int phi2 = (mhi >> 1) * 2 + (mhi & 1);
        #pragma unroll
        for (int nb = 0; nb < 8; ++nb) {
            const int n0 = q * 64 + nb * 8 + 2 * t;
            const float bb0 = b1[n0], bb1 = b1[n0 + 1];
            ((float*)&sE1[n0    ][0])[plo2] = fmaxf(acc[nb][0] + bb0, 0.f);
            ((float*)&sE1[n0 + 1][0])[plo2] = fmaxf(acc[nb][1] + bb1, 0.f);
            ((float*)&sE1[n0    ][0])[phi2] = fmaxf(acc[nb][2] + bb0, 0.f);
            ((float*)&sE1[n0 + 1][0])[phi2] = fmaxf(acc[nb][3] + bb1, 0.f);
        }
    }
    __syncthreads();

    // ========== stage 2: enc2 = relu(enc1 @ W2 + b2) — FFMA2 (R6) ==========
    const int rg = tid >> 6;          // 0..3 -> pairs p0..p0+3
    const int cg = tid & 63;          // cols c0..c0+3
    const int p0 = rg * 4;
    const int c0 = cg * 4;
    {
        ull acc[4][4];
        #pragma unroll
        for (int p = 0; p < 4; ++p)
            #pragma unroll
            for (int c = 0; c < 4; ++c) acc[p][c] = 0ull;

        #pragma unroll 4
        for (int k = 0; k < 256; ++k) {
            const float4 wv = *(const float4*)(W2 + k * 256 + c0);
            const ull wd0 = packf2(wv.x, wv.x);
            const ull wd1 = packf2(wv.y, wv.y);
            const ull wd2 = packf2(wv.z, wv.z);
            const ull wd3 = packf2(wv.w, wv.w);
            const ulonglong2 sA = *(const ulonglong2*)&sE1[k][p0];
            const ulonglong2 sB = *(const ulonglong2*)&sE1[k][p0 + 2];
            ffma2(acc[0][0], sA.x, wd0); ffma2(acc[0][1], sA.x, wd1);
            ffma2(acc[0][2], sA.x, wd2); ffma2(acc[0][3], sA.x, wd3);
            ffma2(acc[1][0], sA.y, wd0); ffma2(acc[1][1], sA.y, wd1);
            ffma2(acc[1][2], sA.y, wd2); ffma2(acc[1][3], sA.y, wd3);
            ffma2(acc[2][0], sB.x, wd0); ffma2(acc[2][1], sB.x, wd1);
            ffma2(acc[2][2], sB.x, wd2); ffma2(acc[2][3], sB.x, wd3);
            ffma2(acc[3][0], sB.y, wd0); ffma2(acc[3][1], sB.y, wd1);
            ffma2(acc[3][2], sB.y, wd2); ffma2(acc[3][3], sB.y, wd3);
        }
        __syncthreads();              // region0 (sA) fully dead -> sE2 may overlay

        const float4 bb = *(const float4*)(b2 + c0);
        const float bc[4] = {bb.x, bb.y, bb.z, bb.w};
        #pragma unroll
        for (int c = 0; c < 4; ++c)
            #pragma unroll
            for (int p = 0; p < 4; ++p) {
                float2 v = unpackf2(acc[p][c]);
                sE2[c0 + c][p0 + p] =
                    make_float2(fmaxf(v.x + bc[c], 0.f), fmaxf(v.y + bc[c], 0.f));
            }
    }
    __syncthreads();

    // ======= stage 3: q = tanh(enc2 @ Wq + bq); part = q . Wh — (R6) =======
    float part;
    {
        const int rg3 = tid >> 4;     // pair 0..15
        const int cg3 = tid & 15;
        const int c3  = cg3 * 4;

        ull a3[4] = {0ull, 0ull, 0ull, 0ull};
        #pragma unroll 4
        for (int k = 0; k < 256; ++k) {
            const float4 wv = *(const float4*)(Wq + k * 64 + c3);
            const ull sp = *(const ull*)&sE2[k][rg3];    // LDS.64 broadcast
            ffma2(a3[0], sp, packf2(wv.x, wv.x));
            ffma2(a3[1], sp, packf2(wv.y, wv.y));
            ffma2(a3[2], sp, packf2(wv.z, wv.z));
            ffma2(a3[3], sp, packf2(wv.w, wv.w));
        }
        const float4 bqv = *(const float4*)(bq + c3);
        const float4 whv = *(const float4*)(Wh + c3);
        const float bqa[4] = {bqv.x, bqv.y, bqv.z, bqv.w};
        const float wha[4] = {whv.x, whv.y, whv.z, whv.w};
        part = 0.f;
        #pragma unroll
        for (int c = 0; c < 4; ++c) {
            float2 v = unpackf2(a3[c]);
            part += (tanhf(v.x + bqa[c]) + tanhf(v.y + bqa[c])) * wha[c];
        }
    }

    // ---- block reduce (fixed order) ----
    #pragma unroll
    for (int o = 16; o > 0; o >>= 1)
        part += __shfl_down_sync(0xffffffffu, part, o);
    if (lane == 0) sRed[w] = part;
    __syncthreads();

    if (tid == 0) {
        float tot = 0.f;
        #pragma unroll
        for (int i = 0; i < 8; ++i) tot += sRed[i];
        g_partials[blockIdx.x] = tot;
        __threadfence();
        unsigned int c = atomicAdd(&g_count, 1u);
        sIsLast = (c == NBLK - 1u);
    }
    __syncthreads();

    // ---- last-done block: deterministic final reduction ----
    if (sIsLast) {
        volatile float* gp = g_partials;
        float v = gp[tid];                       // 256 partials, fixed order
        #pragma unroll
        for (int o = 16; o > 0; o >>= 1)
            v += __shfl_down_sync(0xffffffffu, v, o);
        if (lane == 0) sRed[w] = v;
        __syncthreads();
        if (tid == 0) {
            float t = 0.f;
            #pragma unroll
            for (int i = 0; i < 8; ++i) t += sRed[i];
            out[0] = t + bh[0];
            g_count = 0;                          // self-reset for graph replay
        }
    }
}

extern "C" void kernel_launch(void* const* d_in, const int* in_sizes, int n_in,
                              void* d_out, int out_size)
{
    const float* S  = (const float*)d_in[0];
    const float* W1 = (const float*)d_in[1];
    const float* b1 = (const float*)d_in[2];
    const float* W2 = (const float*)d_in[3];
    const float* b2 = (const float*)d_in[4];
    const float* Wq = (const float*)d_in[5];
    const float* bq = (const float*)d_in[6];
    const float* Wh = (const float*)d_in[7];
    const float* bh = (const float*)d_in[8];
    float* out = (float*)d_out;

    const int dynsm = 65536 + 256 * PITCH * (int)sizeof(float2);   // 102400 B
    cudaFuncSetAttribute(fused_mlp_kernel,
                         cudaFuncAttributeMaxDynamicSharedMemorySize, dynsm);

    prep_W1_kernel<<<64, 512>>>(W1);
    fused_mlp_kernel<<<NBLK, NTHREADS, dynsm>>>(S, b1, W2, b2, Wq, bq, Wh, bh, out);
}

// round 9
// speedup vs baseline: 3.2697x; 1.3574x over previous
#include <cuda_runtime.h>
#include <cuda_bf16.h>

// UnifiedQuantumRegressor — tensor-core fused MLP + reduction (stages 1+2 mma).
//
// Algebra (verified since R1): all edge weights are 1.0 -> mean_w == 1.0
// exactly -> attn == q_out; the O(N^2) fidelity stage is dead.
// out = (sum_i tanh(relu(relu(s_i@W1+b1)@W2+b2)@Wq+bq)) @ Wh + bh
//
// Stages 1+2: mma.sync m16n8k16 bf16, 3-pass split-compensated
//   (Ahi*Bhi + Ahi*Blo + Alo*Bhi, fp32 accum) -> ~2^-17 effective precision.
//   W1/W2 pre-split+packed into B-fragment order by a prep kernel.
//   enc1 is written by the stage-1 epilogue directly in bf16 hi/lo A-fragment
//   layout (thread's (n0,n0+1) accumulator pair == one A-word; s2=wq, half=nb).
// Stage 3: f32x2 FFMA2 row-pair engine (validated R6/R8).
// 512 thr/CTA, warp-owns-16-cols: B fragments read once per CTA.

#define NTHREADS 512
#define TM       32
#define NBLK     256          // 8192 / 32
#define PITCH    18           // float2 per k-row of sE2: 16 pairs + pad

// Packed B-fragments {bhi0,bhi1,blo0,blo1}:
//   W1: [32 ksteps][32 n8][32 lanes]   W2: [16 ksteps][32 n8][32 lanes]
__device__ uint4        g_W1pack[32 * 32 * 32];     // 512 KB
__device__ uint4        g_W2pack[16 * 32 * 32];     // 256 KB
__device__ float        g_partials[NBLK];
__device__ unsigned int g_count;

typedef unsigned long long ull;

static __device__ __forceinline__ ull packf2(float lo, float hi) {
    ull r; asm("mov.b64 %0, {%1, %2};" : "=l"(r) : "f"(lo), "f"(hi)); return r;
}
static __device__ __forceinline__ void ffma2(ull& acc, ull a, ull b) {
    asm("fma.rn.f32x2 %0, %1, %2, %0;" : "+l"(acc) : "l"(a), "l"(b));
}
static __device__ __forceinline__ float2 unpackf2(ull v) {
    float2 f; asm("mov.b64 {%0, %1}, %2;" : "=f"(f.x), "=f"(f.y) : "l"(v)); return f;
}
static __device__ __forceinline__ unsigned pack_bf2(float a, float b) {
    __nv_bfloat162 h; h.x = __float2bfloat16(a); h.y = __float2bfloat16(b);
    return *(unsigned*)&h;
}
static __device__ __forceinline__ float bf_res(float x) {
    return x - __bfloat162float(__float2bfloat16(x));
}
static __device__ __forceinline__ void mma_bf16(float* d,
    unsigned a0, unsigned a1, unsigned a2, unsigned a3,
    unsigned b0, unsigned b1)
{
    asm volatile(
        "mma.sync.aligned.m16n8k16.row.col.f32.bf16.bf16.f32 "
        "{%0,%1,%2,%3}, {%4,%5,%6,%7}, {%8,%9}, {%0,%1,%2,%3};"
        : "+f"(d[0]), "+f"(d[1]), "+f"(d[2]), "+f"(d[3])
        : "r"(a0), "r"(a1), "r"(a2), "r"(a3), "r"(b0), "r"(b1));
}

// ---- prep: split W1/W2 into bf16 hi/lo, pack in B-fragment order ----
__global__ __launch_bounds__(512) void prep_W_kernel(
    const float* __restrict__ W1, const float* __restrict__ W2)
{
    int idx = blockIdx.x * blockDim.x + threadIdx.x;     // 0 .. 49151
    const float* W;
    uint4* dst;
    int li;
    if (idx < 32 * 32 * 32) { W = W1; dst = g_W1pack; li = idx; }
    else if (idx < 48 * 32 * 32) { W = W2; dst = g_W2pack; li = idx - 32 * 32 * 32; }
    else return;
    const int l  = li & 31;
    const int nb = (li >> 5) & 31;
    const int s  = li >> 10;
    const int g = l >> 2, t = l & 3;
    const int n  = nb * 8 + g;
    const int k0 = s * 16 + 2 * t;
    const float w00 = W[(k0    ) * 256 + n];
    const float w01 = W[(k0 + 1) * 256 + n];
    const float w10 = W[(k0 + 8) * 256 + n];
    const float w11 = W[(k0 + 9) * 256 + n];
    uint4 v;
    v.x = pack_bf2(w00, w01);
    v.y = pack_bf2(w10, w11);
    v.z = pack_bf2(bf_res(w00), bf_res(w01));
    v.w = pack_bf2(bf_res(w10), bf_res(w11));
    dst[li] = v;
}

__global__ __launch_bounds__(NTHREADS) void fused_mlp_kernel(
    const float* __restrict__ S,   // [8192,512]
    const float* __restrict__ b1,  // [256]
    const float* __restrict__ b2,  // [256]
    const float* __restrict__ Wq,  // [256,64]
    const float* __restrict__ bq,  // [64]
    const float* __restrict__ Wh,  // [64]
    const float* __restrict__ bh,  // [1]
    float* __restrict__ out)
{
    extern __shared__ unsigned char dynsm[];
    // [0, 32768):      sA1hi [32 s][32 r][4 t] uint2  ->  later sA2hi(16K)+sA2lo(16K)
    // [32768, 69632):  sA1lo (32KB)                   ->  later sE2 [256][PITCH] (36KB)
    uint2* sA1hi = (uint2*)dynsm;
    uint2* sA1lo = (uint2*)(dynsm + 32768);
    uint2* sA2hi = (uint2*)dynsm;
    uint2* sA2lo = (uint2*)(dynsm + 16384);
    float2 (*sE2)[PITCH] = (float2(*)[PITCH])(dynsm + 32768);
    __shared__ float sRed[16];
    __shared__ int   sIsLast;

    const int tid  = threadIdx.x;
    const int wq   = tid >> 5;          // warp 0..15: owns cols [wq*16, wq*16+16)
    const int lane = tid & 31;
    const int g = lane >> 2, t = lane & 3;
    const int row0 = blockIdx.x * TM;

    // ---- stage S tile [32 x 512] into smem, split bf16 hi/lo, frag layout ----
    {
        const int r  = tid >> 4;            // 0..31
        const int s0 = (tid & 15) * 2;      // 2 ksteps per thread
        const float* Srow = S + (size_t)(row0 + r) * 512;
        #pragma unroll
        for (int i = 0; i < 2; ++i) {
            const int s = s0 + i;
            const float4 x0 = *(const float4*)(Srow + s * 16);
            const float4 x1 = *(const float4*)(Srow + s * 16 + 4);
            const float4 x2 = *(const float4*)(Srow + s * 16 + 8);
            const float4 x3 = *(const float4*)(Srow + s * 16 + 12);
            const int base = s * 128 + r * 4;
            sA1hi[base + 0] = make_uint2(pack_bf2(x0.x, x0.y), pack_bf2(x2.x, x2.y));
            sA1hi[base + 1] = make_uint2(pack_bf2(x0.z, x0.w), pack_bf2(x2.z, x2.w));
            sA1hi[base + 2] = make_uint2(pack_bf2(x1.x, x1.y), pack_bf2(x3.x, x3.y));
            sA1hi[base + 3] = make_uint2(pack_bf2(x1.z, x1.w), pack_bf2(x3.z, x3.w));
            sA1lo[base + 0] = make_uint2(pack_bf2(bf_res(x0.x), bf_res(x0.y)),
                                         pack_bf2(bf_res(x2.x), bf_res(x2.y)));
            sA1lo[base + 1] = make_uint2(pack_bf2(bf_res(x0.z), bf_res(x0.w)),
                                         pack_bf2(bf_res(x2.z), bf_res(x2.w)));
            sA1lo[base + 2] = make_uint2(pack_bf2(bf_res(x1.x), bf_res(x1.y)),
                                         pack_bf2(bf_res(x3.x), bf_res(x3.y)));
            sA1lo[base + 3] = make_uint2(pack_bf2(bf_res(x1.z), bf_res(x1.w)),
                                         pack_bf2(bf_res(x3.z), bf_res(x3.w)));
        }
    }
    __syncthreads();

    // ============ stage 1: enc1 = relu(S @ W1 + b1) — tensor ============
    float acc1[2][2][4];                  // [mt][nb][frag]
    {
        #pragma unroll
        for (int mt = 0; mt < 2; ++mt)
            #pragma unroll
            for (int nb = 0; nb < 2; ++nb)
                #pragma unroll
                for (int j = 0; j < 4; ++j) acc1[mt][nb][j] = 0.f;

        #pragma unroll 1
        for (int s = 0; s < 32; ++s) {
            const uint4* bp = g_W1pack + ((s * 32 + wq * 2) * 32 + lane);
            const uint4 B0 = bp[0];
            const uint4 B1 = bp[32];
            #pragma unroll
            for (int mt = 0; mt < 2; ++mt) {
                const int rA0 = s * 128 + (mt * 16 + g) * 4 + t;
                const uint2 Ah0 = sA1hi[rA0];
                const uint2 Ah1 = sA1hi[rA0 + 32];
                const uint2 Al0 = sA1lo[rA0];
                const uint2 Al1 = sA1lo[rA0 + 32];
                mma_bf16(acc1[mt][0], Ah0.x, Ah1.x, Ah0.y, Ah1.y, B0.x, B0.y);
                mma_bf16(acc1[mt][0], Ah0.x, Ah1.x, Ah0.y, Ah1.y, B0.z, B0.w);
                mma_bf16(acc1[mt][0], Al0.x, Al1.x, Al0.y, Al1.y, B0.x, B0.y);
                mma_bf16(acc1[mt][1], Ah0.x, Ah1.x, Ah0.y, Ah1.y, B1.x, B1.y);
                mma_bf16(acc1[mt][1], Ah0.x, Ah1.x, Ah0.y, Ah1.y, B1.z, B1.w);
                mma_bf16(acc1[mt][1], Al0.x, Al1.x, Al0.y, Al1.y, B1.x, B1.y);
            }
        }
    }
    __syncthreads();                       // sA1 consumed; overlay regions free

    // epilogue 1: bias+relu -> enc1 in bf16 hi/lo A-fragment layout (sA2)
    // thread's (n0, n0+1) = one A-word: s2 = wq, word-half = nb, t2 = t.
    {
        #pragma unroll
        for (int nb = 0; nb < 2; ++nb) {
            const int n0 = wq * 16 + nb * 8 + 2 * t;
            const float bb0 = b1[n0], bb1 = b1[n0 + 1];
            #pragma unroll
            for (int mt = 0; mt < 2; ++mt) {
                const int mlo = mt * 16 + g;
                const float vl0 = fmaxf(acc1[mt][nb][0] + bb0, 0.f);
                const float vl1 = fmaxf(acc1[mt][nb][1] + bb1, 0.f);
                const float vh0 = fmaxf(acc1[mt][nb][2] + bb0, 0.f);
                const float vh1 = fmaxf(acc1[mt][nb][3] + bb1, 0.f);
                const int ilo = wq * 128 + mlo * 4 + t;
                const int ihi = ilo + 32;                       // row +8
                ((unsigned*)&sA2hi[ilo])[nb] = pack_bf2(vl0, vl1);
                ((unsigned*)&sA2hi[ihi])[nb] = pack_bf2(vh0, vh1);
                ((unsigned*)&sA2lo[ilo])[nb] = pack_bf2(bf_res(vl0), bf_res(vl1));
                ((unsigned*)&sA2lo[ihi])[nb] = pack_bf2(bf_res(vh0), bf_res(vh1));
            }
        }
    }
    __syncthreads();

    // ============ stage 2: enc2 = relu(enc1 @ W2 + b2) — tensor ============
    float acc2[2][2][4];
    {
        #pragma unroll
        for (int mt = 0; mt < 2; ++mt)
            #pragma unroll
            for (int nb = 0; nb < 2; ++nb)
                #pragma unroll
                for (int j = 0; j < 4; ++j) acc2[mt][nb][j] = 0.f;

        #pragma unroll 1
        for (int s = 0; s < 16; ++s) {
            const uint4* bp = g_W2pack + ((s * 32 + wq * 2) * 32 + lane);
            const uint4 B0 = bp[0];
            const uint4 B1 = bp[32];
            #pragma unroll
            for (int mt = 0; mt < 2; ++mt) {
                const int rA0 = s * 128 + (mt * 16 + g) * 4 + t;
                const uint2 Ah0 = sA2hi[rA0];
                const uint2 Ah1 = sA2hi[rA0 + 32];
                const uint2 Al0 = sA2lo[rA0];
                const uint2 Al1 = sA2lo[rA0 + 32];
                mma_bf16(acc2[mt][0], Ah0.x, Ah1.x, Ah0.y, Ah1.y, B0.x, B0.y);
                mma_bf16(acc2[mt][0], Ah0.x, Ah1.x, Ah0.y, Ah1.y, B0.z, B0.w);
                mma_bf16(acc2[mt][0], Al0.x, Al1.x, Al0.y, Al1.y, B0.x, B0.y);
                mma_bf16(acc2[mt][1], Ah0.x, Ah1.x, Ah0.y, Ah1.y, B1.x, B1.y);
                mma_bf16(acc2[mt][1], Ah0.x, Ah1.x, Ah0.y, Ah1.y, B1.z, B1.w);
                mma_bf16(acc2[mt][1], Al0.x, Al1.x, Al0.y, Al1.y, B1.x, B1.y);
            }
        }
    }
    __syncthreads();                       // sA2 consumed; sE2 region free

    // epilogue 2: bias+relu -> sE2[col][row] (f32 pair layout for stage 3)
    {
        #pragma unroll
        for (int nb = 0; nb < 2; ++nb) {
            const int n0 = wq * 16 + nb * 8 + 2 * t;
            const float bb0 = b2[n0], bb1 = b2[n0 + 1];
            #pragma unroll
            for (int mt = 0; mt < 2; ++mt) {
                const int mlo = mt * 16 + g;
                const int mhi = mlo + 8;
                ((float*)&sE2[n0    ][0])[mlo] = fmaxf(acc2[mt][nb][0] + bb0, 0.f);
                ((float*)&sE2[n0 + 1][0])[mlo] = fmaxf(acc2[mt][nb][1] + bb1, 0.f);
                ((float*)&sE2[n0    ][0])[mhi] = fmaxf(acc2[mt][nb][2] + bb0, 0.f);
                ((float*)&sE2[n0 + 1][0])[mhi] = fmaxf(acc2[mt][nb][3] + bb1, 0.f);
            }
        }
    }
    __syncthreads();

    // ======= stage 3: q = tanh(enc2 @ Wq + bq); part = q . Wh — FFMA2 =======
    float part;
    {
        const int rg3 = tid >> 5;          // pair 0..15 (rows 2rg3, 2rg3+1)
        const int c3  = (tid & 31) * 2;    // 2 cols per lane

        ull a3[2] = {0ull, 0ull};
        #pragma unroll 4
        for (int k = 0; k < 256; ++k) {
            const float2 wv = *(const float2*)(Wq + k * 64 + c3);
            const ull sp = *(const ull*)&sE2[k][rg3];   // LDS.64 broadcast
            ffma2(a3[0], sp, packf2(wv.x, wv.x));
            ffma2(a3[1], sp, packf2(wv.y, wv.y));
        }
        const float2 bq2 = *(const float2*)(bq + c3);
        const float2 wh2 = *(const float2*)(Wh + c3);
        const float2 v0 = unpackf2(a3[0]);
        const float2 v1 = unpackf2(a3[1]);
        part = (tanhf(v0.x + bq2.x) + tanhf(v0.y + bq2.x)) * wh2.x
             + (tanhf(v1.x + bq2.y) + tanhf(v1.y + bq2.y)) * wh2.y;
    }

    // ---- block reduce (fixed order) ----
    #pragma unroll
    for (int o = 16; o > 0; o >>= 1)
        part += __shfl_down_sync(0xffffffffu, part, o);
    if (lane == 0) sRed[wq] = part;
    __syncthreads();

    if (tid == 0) {
        float tot = 0.f;
        #pragma unroll
        for (int i = 0; i < 16; ++i) tot += sRed[i];
        g_partials[blockIdx.x] = tot;
        __threadfence();
        unsigned int c = atomicAdd(&g_count, 1u);
        sIsLast = (c == NBLK - 1u);
    }
    __syncthreads();

    // ---- last-done block: deterministic final reduction ----
    if (sIsLast) {
        volatile float* gp = g_partials;
        float v = (tid < NBLK) ? gp[tid] : 0.f;   // 256 partials, fixed order
        #pragma unroll
        for (int o = 16; o > 0; o >>= 1)
            v += __shfl_down_sync(0xffffffffu, v, o);
        if (lane == 0) sRed[wq] = v;
        __syncthreads();
        if (tid == 0) {
            float tfin = 0.f;
            #pragma unroll
            for (int i = 0; i < 16; ++i) tfin += sRed[i];
            out[0] = tfin + bh[0];
            g_count = 0;                           // self-reset for graph replay
        }
    }
}

extern "C" void kernel_launch(void* const* d_in, const int* in_sizes, int n_in,
                              void* d_out, int out_size)
{
    const float* S  = (const float*)d_in[0];
    const float* W1 = (const float*)d_in[1];
    const float* b1 = (const float*)d_in[2];
    const float* W2 = (const float*)d_in[3];
    const float* b2 = (const float*)d_in[4];
    const float* Wq = (const float*)d_in[5];
    const float* bq = (const float*)d_in[6];
    const float* Wh = (const float*)d_in[7];
    const float* bh = (const float*)d_in[8];
    float* out = (float*)d_out;

    const int dynsm = 69632;    // 32KB frag region + 36KB sE2 region
    cudaFuncSetAttribute(fused_mlp_kernel,
                         cudaFuncAttributeMaxDynamicSharedMemorySize, dynsm);

    prep_W_kernel<<<96, 512>>>(W1, W2);
    fused_mlp_kernel<<<NBLK, NTHREADS, dynsm>>>(S, b1, b2, Wq, bq, Wh, bh, out);
}

// round 11
// speedup vs baseline: 3.4018x; 1.0404x over previous
#include <cuda_runtime.h>
#include <cuda_bf16.h>

// UnifiedQuantumRegressor — tensor-core fused MLP + reduction (stages 1+2 mma).
//
// Algebra (verified since R1): all edge weights are 1.0 -> mean_w == 1.0
// exactly -> attn == q_out; the O(N^2) fidelity stage is dead.
// out = (sum_i tanh(relu(relu(s_i@W1+b1)@W2+b2)@Wq+bq)) @ Wh + bh
//
// Stages 1+2: mma.sync m16n8k16 bf16, 3-pass split-compensated
//   (Ahi*Bhi + Ahi*Blo + Alo*Bhi, fp32 accum) -> ~2^-17 effective precision.
// R10 change: 8 warps/CTA, warp owns 32 cols (nb=4) -> A-fragment loads
//   amortized over 2x MMAs: 1.33 L1-wavefronts/MMA (was 2.0). 256 thr/CTA.
// Stage 3: f32x2 FFMA2 row-pair engine (validated R6/R8/R9).

#define NTHREADS 256
#define TM       32
#define NBLK     256          // 8192 / 32
#define PITCH    18           // float2 per k-row of sE2: 16 pairs + pad

// Packed B-fragments {bhi0,bhi1,blo0,blo1}:
//   W1: [32 ksteps][32 n8][32 lanes]   W2: [16 ksteps][32 n8][32 lanes]
__device__ uint4        g_W1pack[32 * 32 * 32];     // 512 KB
__device__ uint4        g_W2pack[16 * 32 * 32];     // 256 KB
__device__ float        g_partials[NBLK];
__device__ unsigned int g_count;

typedef unsigned long long ull;

static __device__ __forceinline__ ull packf2(float lo, float hi) {
    ull r; asm("mov.b64 %0, {%1, %2};" : "=l"(r) : "f"(lo), "f"(hi)); return r;
}
static __device__ __forceinline__ void ffma2(ull& acc, ull a, ull b) {
    asm("fma.rn.f32x2 %0, %1, %2, %0;" : "+l"(acc) : "l"(a), "l"(b));
}
static __device__ __forceinline__ float2 unpackf2(ull v) {
    float2 f; asm("mov.b64 {%0, %1}, %2;" : "=f"(f.x), "=f"(f.y) : "l"(v)); return f;
}
static __device__ __forceinline__ unsigned pack_bf2(float a, float b) {
    __nv_bfloat162 h; h.x = __float2bfloat16(a); h.y = __float2bfloat16(b);
    return *(unsigned*)&h;
}
static __device__ __forceinline__ float bf_res(float x) {
    return x - __bfloat162float(__float2bfloat16(x));
}
static __device__ __forceinline__ void mma_bf16(float* d,
    unsigned a0, unsigned a1, unsigned a2, unsigned a3,
    unsigned b0, unsigned b1)
{
    asm volatile(
        "mma.sync.aligned.m16n8k16.row.col.f32.bf16.bf16.f32 "
        "{%0,%1,%2,%3}, {%4,%5,%6,%7}, {%8,%9}, {%0,%1,%2,%3};"
        : "+f"(d[0]), "+f"(d[1]), "+f"(d[2]), "+f"(d[3])
        : "r"(a0), "r"(a1), "r"(a2), "r"(a3), "r"(b0), "r"(b1));
}

// ---- prep: split W1/W2 into bf16 hi/lo, pack in B-fragment order ----
__global__ __launch_bounds__(512) void prep_W_kernel(
    const float* __restrict__ W1, const float* __restrict__ W2)
{
    int idx = blockIdx.x * blockDim.x + threadIdx.x;     // 0 .. 49151
    const float* W;
    uint4* dst;
    int li;
    if (idx < 32 * 32 * 32) { W = W1; dst = g_W1pack; li = idx; }
    else if (idx < 48 * 32 * 32) { W = W2; dst = g_W2pack; li = idx - 32 * 32 * 32; }
    else return;
    const int l  = li & 31;
    const int nb = (li >> 5) & 31;
    const int s  = li >> 10;
    const int g = l >> 2, t = l & 3;
    const int n  = nb * 8 + g;
    const int k0 = s * 16 + 2 * t;
    const float w00 = W[(k0    ) * 256 + n];
    const float w01 = W[(k0 + 1) * 256 + n];
    const float w10 = W[(k0 + 8) * 256 + n];
    const float w11 = W[(k0 + 9) * 256 + n];
    uint4 v;
    v.x = pack_bf2(w00, w01);
    v.y = pack_bf2(w10, w11);
    v.z = pack_bf2(bf_res(w00), bf_res(w01));
    v.w = pack_bf2(bf_res(w10), bf_res(w11));
    dst[li] = v;
}

__global__ __launch_bounds__(NTHREADS) void fused_mlp_kernel(
    const float* __restrict__ S,   // [8192,512]
    const float* __restrict__ b1,  // [256]
    const float* __restrict__ b2,  // [256]
    const float* __restrict__ Wq,  // [256,64]
    const float* __restrict__ bq,  // [64]
    const float* __restrict__ Wh,  // [64]
    const float* __restrict__ bh,  // [1]
    float* __restrict__ out)
{
    extern __shared__ unsigned char dynsm[];
    // [0, 32768):      sA1hi [32 s][32 r][4 t] uint2  ->  later sA2hi(16K)+sA2lo(16K)
    // [32768, 69632):  sA1lo (32KB)                   ->  later sE2 [256][PITCH] (36KB)
    uint2* sA1hi = (uint2*)dynsm;
    uint2* sA1lo = (uint2*)(dynsm + 32768);
    uint2* sA2hi = (uint2*)dynsm;                    // [16 s2][32 r][4 t]
    uint2* sA2lo = (uint2*)(dynsm + 16384);
    float2 (*sE2)[PITCH] = (float2(*)[PITCH])(dynsm + 32768);
    __shared__ float sRed[8];
    __shared__ int   sIsLast;

    const int tid  = threadIdx.x;
    const int wq   = tid >> 5;          // warp 0..7: owns cols [wq*32, wq*32+32)
    const int lane = tid & 31;
    const int g = lane >> 2, t = lane & 3;
    const int row0 = blockIdx.x * TM;

    // ---- stage S tile [32 x 512] into smem, split bf16 hi/lo, frag layout ----
    {
        const int r  = tid >> 3;            // 0..31
        const int s0 = (tid & 7) * 4;       // 4 ksteps per thread
        const float* Srow = S + (size_t)(row0 + r) * 512;
        #pragma unroll
        for (int i = 0; i < 4; ++i) {
            const int s = s0 + i;
            const float4 x0 = *(const float4*)(Srow + s * 16);
            const float4 x1 = *(const float4*)(Srow + s * 16 + 4);
            const float4 x2 = *(const float4*)(Srow + s * 16 + 8);
            const float4 x3 = *(const float4*)(Srow + s * 16 + 12);
            const int base = s * 128 + r * 4;
            sA1hi[base + 0] = make_uint2(pack_bf2(x0.x, x0.y), pack_bf2(x2.x, x2.y));
            sA1hi[base + 1] = make_uint2(pack_bf2(x0.z, x0.w), pack_bf2(x2.z, x2.w));
            sA1hi[base + 2] = make_uint2(pack_bf2(x1.x, x1.y), pack_bf2(x3.x, x3.y));
            sA1hi[base + 3] = make_uint2(pack_bf2(x1.z, x1.w), pack_bf2(x3.z, x3.w));
            sA1lo[base + 0] = make_uint2(pack_bf2(bf_res(x0.x), bf_res(x0.y)),
                                         pack_bf2(bf_res(x2.x), bf_res(x2.y)));
            sA1lo[base + 1] = make_uint2(pack_bf2(bf_res(x0.z), bf_res(x0.w)),
                                         pack_bf2(bf_res(x2.z), bf_res(x2.w)));
            sA1lo[base + 2] = make_uint2(pack_bf2(bf_res(x1.x), bf_res(x1.y)),
                                         pack_bf2(bf_res(x3.x), bf_res(x3.y)));
            sA1lo[base + 3] = make_uint2(pack_bf2(bf_res(x1.z), bf_res(x1.w)),
                                         pack_bf2(bf_res(x3.z), bf_res(x3.w)));
        }
    }
    __syncthreads();

    // ============ stage 1: enc1 = relu(S @ W1 + b1) — tensor ============
    float acc1[2][4][4];                  // [mt][nbi][frag]
    {
        #pragma unroll
        for (int mt = 0; mt < 2; ++mt)
            #pragma unroll
            for (int nbi = 0; nbi < 4; ++nbi)
                #pragma unroll
                for (int j = 0; j < 4; ++j) acc1[mt][nbi][j] = 0.f;

        #pragma unroll 1
        for (int s = 0; s < 32; ++s) {
            const uint4* bp = g_W1pack + ((s * 32 + wq * 4) * 32 + lane);
            uint4 B[4];
            #pragma unroll
            for (int nbi = 0; nbi < 4; ++nbi) B[nbi] = bp[nbi * 32];
            #pragma unroll
            for (int mt = 0; mt < 2; ++mt) {
                const int rA0 = s * 128 + (mt * 16 + g) * 4 + t;
                const uint2 Ah0 = sA1hi[rA0];
                const uint2 Ah1 = sA1hi[rA0 + 32];
                const uint2 Al0 = sA1lo[rA0];
                const uint2 Al1 = sA1lo[rA0 + 32];
                #pragma unroll
                for (int nbi = 0; nbi < 4; ++nbi) {
                    mma_bf16(acc1[mt][nbi], Ah0.x, Ah1.x, Ah0.y, Ah1.y, B[nbi].x, B[nbi].y);
                    mma_bf16(acc1[mt][nbi], Ah0.x, Ah1.x, Ah0.y, Ah1.y, B[nbi].z, B[nbi].w);
                    mma_bf16(acc1[mt][nbi], Al0.x, Al1.x, Al0.y, Al1.y, B[nbi].x, B[nbi].y);
                }
            }
        }
    }
    __syncthreads();                       // sA1 consumed; overlay regions free

    // epilogue 1: bias+relu -> enc1 in bf16 hi/lo A-fragment layout (sA2)
    // col n0 = wq*32 + nbi*8 + 2t  ->  s2 = 2*wq + (nbi>>1), word-half = nbi&1.
    {
        #pragma unroll
        for (int nbi = 0; nbi < 4; ++nbi) {
            const int n0 = wq * 32 + nbi * 8 + 2 * t;
            const float bb0 = b1[n0], bb1 = b1[n0 + 1];
            const int s2 = 2 * wq + (nbi >> 1);
            const int half = nbi & 1;
            #pragma unroll
            for (int mt = 0; mt < 2; ++mt) {
                const int mlo = mt * 16 + g;
                const float vl0 = fmaxf(acc1[mt][nbi][0] + bb0, 0.f);
                const float vl1 = fmaxf(acc1[mt][nbi][1] + bb1, 0.f);
                const float vh0 = fmaxf(acc1[mt][nbi][2] + bb0, 0.f);
                const float vh1 = fmaxf(acc1[mt][nbi][3] + bb1, 0.f);
                const int ilo = s2 * 128 + mlo * 4 + t;
                const int ihi = ilo + 32;                       // row +8
                ((unsigned*)&sA2hi[ilo])[half] = pack_bf2(vl0, vl1);
                ((unsigned*)&sA2hi[ihi])[half] = pack_bf2(vh0, vh1);
                ((unsigned*)&sA2lo[ilo])[half] = pack_bf2(bf_res(vl0), bf_res(vl1));
                ((unsigned*)&sA2lo[ihi])[half] = pack_bf2(bf_res(vh0), bf_res(vh1));
            }
        }
    }
    __syncthreads();

    // ============ stage 2: enc2 = relu(enc1 @ W2 + b2) — tensor ============
    float acc2[2][4][4];
    {
        #pragma unroll
        for (int mt = 0; mt < 2; ++mt)
            #pragma unroll
            for (int nbi = 0; nbi < 4; ++nbi)
                #pragma unroll
                for (int j = 0; j < 4; ++j) acc2[mt][nbi][j] = 0.f;

        #pragma unroll 1
        for (int s = 0; s < 16; ++s) {
            const uint4* bp = g_W2pack + ((s * 32 + wq * 4) * 32 + lane);
            uint4 B[4];
            #pragma unroll
            for (int nbi = 0; nbi < 4; ++nbi) B[nbi] = bp[nbi * 32];
            #pragma unroll
            for (int mt = 0; mt < 2; ++mt) {
                const int rA0 = s * 128 + (mt * 16 + g) * 4 + t;
                const uint2 Ah0 = sA2hi[rA0];
                const uint2 Ah1 = sA2hi[rA0 + 32];
                const uint2 Al0 = sA2lo[rA0];
                const uint2 Al1 = sA2lo[rA0 + 32];
                #pragma unroll
                for (int nbi = 0; nbi < 4; ++nbi) {
                    mma_bf16(acc2[mt][nbi], Ah0.x, Ah1.x, Ah0.y, Ah1.y, B[nbi].x, B[nbi].y);
                    mma_bf16(acc2[mt][nbi], Ah0.x, Ah1.x, Ah0.y, Ah1.y, B[nbi].z, B[nbi].w);
                    mma_bf16(acc2[mt][nbi], Al0.x, Al1.x, Al0.y, Al1.y, B[nbi].x, B[nbi].y);
                }
            }
        }
    }
    __syncthreads();                       // sA2 consumed; sE2 region free

    // epilogue 2: bias+relu -> sE2[col][row] (f32 pair layout for stage 3)
    {
        #pragma unroll
        for (int nbi = 0; nbi < 4; ++nbi) {
            const int n0 = wq * 32 + nbi * 8 + 2 * t;
            const float bb0 = b2[n0], bb1 = b2[n0 + 1];
            #pragma unroll
            for (int mt = 0; mt < 2; ++mt) {
                const int mlo = mt * 16 + g;
                const int mhi = mlo + 8;
                ((float*)&sE2[n0    ][0])[mlo] = fmaxf(acc2[mt][nbi][0] + bb0, 0.f);
                ((float*)&sE2[n0 + 1][0])[mlo] = fmaxf(acc2[mt][nbi][1] + bb1, 0.f);
                ((float*)&sE2[n0    ][0])[mhi] = fmaxf(acc2[mt][nbi][2] + bb0, 0.f);
                ((float*)&sE2[n0 + 1][0])[mhi] = fmaxf(acc2[mt][nbi][3] + bb1, 0.f);
            }
        }
    }
    __syncthreads();

    // ======= stage 3: q = tanh(enc2 @ Wq + bq); part = q . Wh — FFMA2 =======
    float part;
    {
        const int rg3 = tid >> 4;          // pair 0..15 (rows 2rg3, 2rg3+1)
        const int c3  = (tid & 15) * 4;    // 4 cols per lane

        ull a3[4] = {0ull, 0ull, 0ull, 0ull};
        #pragma unroll 4
        for (int k = 0; k < 256; ++k) {
            const float4 wv = *(const float4*)(Wq + k * 64 + c3);
            const ull sp = *(const ull*)&sE2[k][rg3];   // LDS.64 broadcast
            ffma2(a3[0], sp, packf2(wv.x, wv.x));
            ffma2(a3[1], sp, packf2(wv.y, wv.y));
            ffma2(a3[2], sp, packf2(wv.z, wv.z));
            ffma2(a3[3], sp, packf2(wv.w, wv.w));
        }
        const float4 bqv = *(const float4*)(bq + c3);
        const float4 whv = *(const float4*)(Wh + c3);
        const float bqa[4] = {bqv.x, bqv.y, bqv.z, bqv.w};
        const float wha[4] = {whv.x, whv.y, whv.z, whv.w};
        part = 0.f;
        #pragma unroll
        for (int c = 0; c < 4; ++c) {
            float2 v = unpackf2(a3[c]);
            part += (tanhf(v.x + bqa[c]) + tanhf(v.y + bqa[c])) * wha[c];
        }
    }

    // ---- block reduce (fixed order) ----
    #pragma unroll
    for (int o = 16; o > 0; o >>= 1)
        part += __shfl_down_sync(0xffffffffu, part, o);
    if (lane == 0) sRed[wq] = part;
    __syncthreads();

    if (tid == 0) {
        float tot = 0.f;
        #pragma unroll
        for (int i = 0; i < 8; ++i) tot += sRed[i];
        g_partials[blockIdx.x] = tot;
        __threadfence();
        unsigned int c = atomicAdd(&g_count, 1u);
        sIsLast = (c == NBLK - 1u);
    }
    __syncthreads();

    // ---- last-done block: deterministic final reduction ----
    if (sIsLast) {
        volatile float* gp = g_partials;
        float v = gp[tid];                       // 256 partials, fixed order
        #pragma unroll
        for (int o = 16; o > 0; o >>= 1)
            v += __shfl_down_sync(0xffffffffu, v, o);
        if (lane == 0) sRed[wq] = v;
        __syncthreads();
        if (tid == 0) {
            float tfin = 0.f;
            #pragma unroll
            for (int i = 0; i < 8; ++i) tfin += sRed[i];
            out[0] = tfin + bh[0];
            g_count = 0;                           // self-reset for graph replay
        }
    }
}

extern "C" void kernel_launch(void* const* d_in, const int* in_sizes, int n_in,
                              void* d_out, int out_size)
{
    const float* S  = (const float*)d_in[0];
    const float* W1 = (const float*)d_in[1];
    const float* b1 = (const float*)d_in[2];
    const float* W2 = (const float*)d_in[3];
    const float* b2 = (const float*)d_in[4];
    const float* Wq = (const float*)d_in[5];
    const float* bq = (const float*)d_in[6];
    const float* Wh = (const float*)d_in[7];
    const float* bh = (const float*)d_in[8];
    float* out = (float*)d_out;

    const int dynsm = 69632;    // 32KB frag region + 36KB sE2 region
    cudaFuncSetAttribute(fused_mlp_kernel,
                         cudaFuncAttributeMaxDynamicSharedMemorySize, dynsm);

    prep_W_kernel<<<96, 512>>>(W1, W2);
    fused_mlp_kernel<<<NBLK, NTHREADS, dynsm>>>(S, b1, b2, Wq, bq, Wh, bh, out);
}

// round 12
// speedup vs baseline: 4.1117x; 1.2087x over previous
#include <cuda_runtime.h>
#include <cuda_bf16.h>

// UnifiedQuantumRegressor — all-tensor fused MLP + reduction.
//
// Algebra (verified since R1): all edge weights are 1.0 -> mean_w == 1.0
// exactly -> attn == q_out; the O(N^2) fidelity stage is dead.
// out = (sum_i tanh(relu(relu(s_i@W1+b1)@W2+b2)@Wq+bq)) @ Wh + bh
//
// Stages 1+2+3: mma.sync m16n8k16 bf16, 3-pass split-compensated
//   (Ahi*Bhi + Ahi*Blo + Alo*Bhi, fp32 accum) -> ~2^-17 effective precision.
// R12: stage-3 GEMM moved to tensor (was 25% of issue for 7.7% of MACs);
//   B-fragment double-buffer prefetch in every s-loop hides L2 latency.
// Epilogues write activations directly in bf16 hi/lo A-fragment layout.

#define NTHREADS 256
#define TM       32
#define NBLK     256          // 8192 / 32

// Packed B-fragments {bhi0,bhi1,blo0,blo1}:
__device__ uint4        g_W1pack[32 * 32 * 32];     // 512 KB
__device__ uint4        g_W2pack[16 * 32 * 32];     // 256 KB
__device__ uint4        g_WQpack[16 * 8 * 32];      //  64 KB
__device__ float        g_partials[NBLK];
__device__ unsigned int g_count;

static __device__ __forceinline__ unsigned pack_bf2(float a, float b) {
    __nv_bfloat162 h; h.x = __float2bfloat16(a); h.y = __float2bfloat16(b);
    return *(unsigned*)&h;
}
static __device__ __forceinline__ float bf_res(float x) {
    return x - __bfloat162float(__float2bfloat16(x));
}
static __device__ __forceinline__ void mma_bf16(float* d,
    unsigned a0, unsigned a1, unsigned a2, unsigned a3,
    unsigned b0, unsigned b1)
{
    asm volatile(
        "mma.sync.aligned.m16n8k16.row.col.f32.bf16.bf16.f32 "
        "{%0,%1,%2,%3}, {%4,%5,%6,%7}, {%8,%9}, {%0,%1,%2,%3};"
        : "+f"(d[0]), "+f"(d[1]), "+f"(d[2]), "+f"(d[3])
        : "r"(a0), "r"(a1), "r"(a2), "r"(a3), "r"(b0), "r"(b1));
}

// ---- prep: split W1/W2/Wq into bf16 hi/lo, pack in B-fragment order ----
__global__ __launch_bounds__(512) void prep_W_kernel(
    const float* __restrict__ W1, const float* __restrict__ W2,
    const float* __restrict__ Wq)
{
    int idx = blockIdx.x * blockDim.x + threadIdx.x;     // 0 .. 53247
    const float* W;
    uint4* dst;
    int li, nb, s, ncols;
    if (idx < 32 * 32 * 32) {
        W = W1; dst = g_W1pack; li = idx;
        nb = (li >> 5) & 31; s = li >> 10; ncols = 256;
    } else if (idx < 48 * 32 * 32) {
        W = W2; dst = g_W2pack; li = idx - 32 * 32 * 32;
        nb = (li >> 5) & 31; s = li >> 10; ncols = 256;
    } else if (idx < 48 * 32 * 32 + 16 * 8 * 32) {
        W = Wq; dst = g_WQpack; li = idx - 48 * 32 * 32;
        nb = (li >> 5) & 7;  s = li >> 8;  ncols = 64;
    } else return;
    const int l = li & 31;
    const int g = l >> 2, t = l & 3;
    const int n  = nb * 8 + g;
    const int k0 = s * 16 + 2 * t;
    const float w00 = W[(k0    ) * ncols + n];
    const float w01 = W[(k0 + 1) * ncols + n];
    const float w10 = W[(k0 + 8) * ncols + n];
    const float w11 = W[(k0 + 9) * ncols + n];
    uint4 v;
    v.x = pack_bf2(w00, w01);
    v.y = pack_bf2(w10, w11);
    v.z = pack_bf2(bf_res(w00), bf_res(w01));
    v.w = pack_bf2(bf_res(w10), bf_res(w11));
    dst[li] = v;
}

__global__ __launch_bounds__(NTHREADS) void fused_mlp_kernel(
    const float* __restrict__ S,   // [8192,512]
    const float* __restrict__ b1,  // [256]
    const float* __restrict__ b2,  // [256]
    const float* __restrict__ bq,  // [64]
    const float* __restrict__ Wh,  // [64]
    const float* __restrict__ bh,  // [1]
    float* __restrict__ out)
{
    extern __shared__ unsigned char dynsm[];
    // region0 [0,32K):   sA1hi [32 s][32 r][4 t] uint2 -> sA2hi(16K)+sA2lo(16K)
    // region1 [32K,64K): sA1lo                         -> sA3hi(16K)+sA3lo(16K)
    uint2* sA1hi = (uint2*)dynsm;
    uint2* sA1lo = (uint2*)(dynsm + 32768);
    uint2* sA2hi = (uint2*)dynsm;
    uint2* sA2lo = (uint2*)(dynsm + 16384);
    uint2* sA3hi = (uint2*)(dynsm + 32768);
    uint2* sA3lo = (uint2*)(dynsm + 49152);
    __shared__ float sRed[8];
    __shared__ int   sIsLast;

    const int tid  = threadIdx.x;
    const int wq   = tid >> 5;          // warp 0..7
    const int lane = tid & 31;
    const int g = lane >> 2, t = lane & 3;
    const int row0 = blockIdx.x * TM;

    // ---- stage S tile [32 x 512] into smem, split bf16 hi/lo, frag layout ----
    {
        const int r  = tid >> 3;            // 0..31
        const int s0 = (tid & 7) * 4;       // 4 ksteps per thread
        const float* Srow = S + (size_t)(row0 + r) * 512;
        #pragma unroll
        for (int i = 0; i < 4; ++i) {
            const int s = s0 + i;
            const float4 x0 = *(const float4*)(Srow + s * 16);
            const float4 x1 = *(const float4*)(Srow + s * 16 + 4);
            const float4 x2 = *(const float4*)(Srow + s * 16 + 8);
            const float4 x3 = *(const float4*)(Srow + s * 16 + 12);
            const int base = s * 128 + r * 4;
            sA1hi[base + 0] = make_uint2(pack_bf2(x0.x, x0.y), pack_bf2(x2.x, x2.y));
            sA1hi[base + 1] = make_uint2(pack_bf2(x0.z, x0.w), pack_bf2(x2.z, x2.w));
            sA1hi[base + 2] = make_uint2(pack_bf2(x1.x, x1.y), pack_bf2(x3.x, x3.y));
            sA1hi[base + 3] = make_uint2(pack_bf2(x1.z, x1.w), pack_bf2(x3.z, x3.w));
            sA1lo[base + 0] = make_uint2(pack_bf2(bf_res(x0.x), bf_res(x0.y)),
                                         pack_bf2(bf_res(x2.x), bf_res(x2.y)));
            sA1lo[base + 1] = make_uint2(pack_bf2(bf_res(x0.z), bf_res(x0.w)),
                                         pack_bf2(bf_res(x2.z), bf_res(x2.w)));
            sA1lo[base + 2] = make_uint2(pack_bf2(bf_res(x1.x), bf_res(x1.y)),
                                         pack_bf2(bf_res(x3.x), bf_res(x3.y)));
            sA1lo[base + 3] = make_uint2(pack_bf2(bf_res(x1.z), bf_res(x1.w)),
                                         pack_bf2(bf_res(x3.z), bf_res(x3.w)));
        }
    }
    __syncthreads();

    // ============ stage 1: enc1 = relu(S @ W1 + b1) — tensor, B prefetch ============
    float acc1[2][4][4];
    {
        #pragma unroll
        for (int mt = 0; mt < 2; ++mt)
            #pragma unroll
            for (int nbi = 0; nbi < 4; ++nbi)
                #pragma unroll
                for (int j = 0; j < 4; ++j) acc1[mt][nbi][j] = 0.f;

        uint4 B[4];
        {
            const uint4* bp = g_W1pack + ((wq * 4) * 32 + lane);
            #pragma unroll
            for (int nbi = 0; nbi < 4; ++nbi) B[nbi] = bp[nbi * 32];
        }
        #pragma unroll 2
        for (int s = 0; s < 32; ++s) {
            const int sn = (s + 1 < 32) ? s + 1 : 31;
            const uint4* bpn = g_W1pack + ((sn * 32 + wq * 4) * 32 + lane);
            uint4 Bn[4];
            #pragma unroll
            for (int nbi = 0; nbi < 4; ++nbi) Bn[nbi] = bpn[nbi * 32];

            uint2 Ah[2][2], Al[2][2];
            #pragma unroll
            for (int mt = 0; mt < 2; ++mt) {
                const int rA0 = s * 128 + (mt * 16 + g) * 4 + t;
                Ah[mt][0] = sA1hi[rA0]; Ah[mt][1] = sA1hi[rA0 + 32];
                Al[mt][0] = sA1lo[rA0]; Al[mt][1] = sA1lo[rA0 + 32];
            }
            #pragma unroll
            for (int mt = 0; mt < 2; ++mt)
                #pragma unroll
                for (int nbi = 0; nbi < 4; ++nbi) {
                    mma_bf16(acc1[mt][nbi], Ah[mt][0].x, Ah[mt][1].x, Ah[mt][0].y, Ah[mt][1].y, B[nbi].x, B[nbi].y);
                    mma_bf16(acc1[mt][nbi], Ah[mt][0].x, Ah[mt][1].x, Ah[mt][0].y, Ah[mt][1].y, B[nbi].z, B[nbi].w);
                    mma_bf16(acc1[mt][nbi], Al[mt][0].x, Al[mt][1].x, Al[mt][0].y, Al[mt][1].y, B[nbi].x, B[nbi].y);
                }
            #pragma unroll
            for (int nbi = 0; nbi < 4; ++nbi) B[nbi] = Bn[nbi];
        }
    }
    __syncthreads();                       // sA1hi reads done; region0 reusable

    // epilogue 1: bias+relu -> enc1 in bf16 hi/lo A-fragment layout (sA2)
    {
        #pragma unroll
        for (int nbi = 0; nbi < 4; ++nbi) {
            const int n0 = wq * 32 + nbi * 8 + 2 * t;
            const float bb0 = b1[n0], bb1 = b1[n0 + 1];
            const int s2 = 2 * wq + (nbi >> 1);
            const int half = nbi & 1;
            #pragma unroll
            for (int mt = 0; mt < 2; ++mt) {
                const int mlo = mt * 16 + g;
                const float vl0 = fmaxf(acc1[mt][nbi][0] + bb0, 0.f);
                const float vl1 = fmaxf(acc1[mt][nbi][1] + bb1, 0.f);
                const float vh0 = fmaxf(acc1[mt][nbi][2] + bb0, 0.f);
                const float vh1 = fmaxf(acc1[mt][nbi][3] + bb1, 0.f);
                const int ilo = s2 * 128 + mlo * 4 + t;
                const int ihi = ilo + 32;
                ((unsigned*)&sA2hi[ilo])[half] = pack_bf2(vl0, vl1);
                ((unsigned*)&sA2hi[ihi])[half] = pack_bf2(vh0, vh1);
                ((unsigned*)&sA2lo[ilo])[half] = pack_bf2(bf_res(vl0), bf_res(vl1));
                ((unsigned*)&sA2lo[ihi])[half] = pack_bf2(bf_res(vh0), bf_res(vh1));
            }
        }
    }
    __syncthreads();

    // ============ stage 2: enc2 = relu(enc1 @ W2 + b2) — tensor, B prefetch ============
    float acc2[2][4][4];
    {
        #pragma unroll
        for (int mt = 0; mt < 2; ++mt)
            #pragma unroll
            for (int nbi = 0; nbi < 4; ++nbi)
                #pragma unroll
                for (int j = 0; j < 4; ++j) acc2[mt][nbi][j] = 0.f;

        uint4 B[4];
        {
            const uint4* bp = g_W2pack + ((wq * 4) * 32 + lane);
            #pragma unroll
            for (int nbi = 0; nbi < 4; ++nbi) B[nbi] = bp[nbi * 32];
        }
        #pragma unroll 2
        for (int s = 0; s < 16; ++s) {
            const int sn = (s + 1 < 16) ? s + 1 : 15;
            const uint4* bpn = g_W2pack + ((sn * 32 + wq * 4) * 32 + lane);
            uint4 Bn[4];
            #pragma unroll
            for (int nbi = 0; nbi < 4; ++nbi) Bn[nbi] = bpn[nbi * 32];

            uint2 Ah[2][2], Al[2][2];
            #pragma unroll
            for (int mt = 0; mt < 2; ++mt) {
                const int rA0 = s * 128 + (mt * 16 + g) * 4 + t;
                Ah[mt][0] = sA2hi[rA0]; Ah[mt][1] = sA2hi[rA0 + 32];
                Al[mt][0] = sA2lo[rA0]; Al[mt][1] = sA2lo[rA0 + 32];
            }
            #pragma unroll
            for (int mt = 0; mt < 2; ++mt)
                #pragma unroll
                for (int nbi = 0; nbi < 4; ++nbi) {
                    mma_bf16(acc2[mt][nbi], Ah[mt][0].x, Ah[mt][1].x, Ah[mt][0].y, Ah[mt][1].y, B[nbi].x, B[nbi].y);
                    mma_bf16(acc2[mt][nbi], Ah[mt][0].x, Ah[mt][1].x, Ah[mt][0].y, Ah[mt][1].y, B[nbi].z, B[nbi].w);
                    mma_bf16(acc2[mt][nbi], Al[mt][0].x, Al[mt][1].x, Al[mt][0].y, Al[mt][1].y, B[nbi].x, B[nbi].y);
                }
            #pragma unroll
            for (int nbi = 0; nbi < 4; ++nbi) B[nbi] = Bn[nbi];
        }
    }
    // epilogue 2: bias+relu -> enc2 in A-fragment layout (sA3, region1; sA1lo dead).
    // No sync needed: each thread writes only data derived from its own accs,
    // and region1 has no readers until the next __syncthreads().
    {
        #pragma unroll
        for (int nbi = 0; nbi < 4; ++nbi) {
            const int n0 = wq * 32 + nbi * 8 + 2 * t;
            const float bb0 = b2[n0], bb1 = b2[n0 + 1];
            const int s2 = 2 * wq + (nbi >> 1);
            const int half = nbi & 1;
            #pragma unroll
            for (int mt = 0; mt < 2; ++mt) {
                const int mlo = mt * 16 + g;
                const float vl0 = fmaxf(acc2[mt][nbi][0] + bb0, 0.f);
                const float vl1 = fmaxf(acc2[mt][nbi][1] + bb1, 0.f);
                const float vh0 = fmaxf(acc2[mt][nbi][2] + bb0, 0.f);
                const float vh1 = fmaxf(acc2[mt][nbi][3] + bb1, 0.f);
                const int ilo = s2 * 128 + mlo * 4 + t;
                const int ihi = ilo + 32;
                ((unsigned*)&sA3hi[ilo])[half] = pack_bf2(vl0, vl1);
                ((unsigned*)&sA3hi[ihi])[half] = pack_bf2(vh0, vh1);
                ((unsigned*)&sA3lo[ilo])[half] = pack_bf2(bf_res(vl0), bf_res(vl1));
                ((unsigned*)&sA3lo[ihi])[half] = pack_bf2(bf_res(vh0), bf_res(vh1));
            }
        }
    }
    __syncthreads();

    // ====== stage 3: qpre = enc2 @ Wq — tensor; warp wq owns n8-block wq ======
    float acc3[2][4];
    {
        #pragma unroll
        for (int mt = 0; mt < 2; ++mt)
            #pragma unroll
            for (int j = 0; j < 4; ++j) acc3[mt][j] = 0.f;

        uint4 B = g_WQpack[(0 * 8 + wq) * 32 + lane];
        #pragma unroll 2
        for (int s = 0; s < 16; ++s) {
            const int sn = (s + 1 < 16) ? s + 1 : 15;
            const uint4 Bn = g_WQpack[(sn * 8 + wq) * 32 + lane];

            #pragma unroll
            for (int mt = 0; mt < 2; ++mt) {
                const int rA0 = s * 128 + (mt * 16 + g) * 4 + t;
                const uint2 Ah0 = sA3hi[rA0];
                const uint2 Ah1 = sA3hi[rA0 + 32];
                const uint2 Al0 = sA3lo[rA0];
                const uint2 Al1 = sA3lo[rA0 + 32];
                mma_bf16(acc3[mt], Ah0.x, Ah1.x, Ah0.y, Ah1.y, B.x, B.y);
                mma_bf16(acc3[mt], Ah0.x, Ah1.x, Ah0.y, Ah1.y, B.z, B.w);
                mma_bf16(acc3[mt], Al0.x, Al1.x, Al0.y, Al1.y, B.x, B.y);
            }
            B = Bn;
        }
    }

    // epilogue 3: q = tanh(qpre + bq); part = q . Wh  (each D element unique)
    float part;
    {
        const int n0 = wq * 8 + 2 * t;
        const float bq0 = bq[n0], bq1 = bq[n0 + 1];
        const float wh0 = Wh[n0], wh1 = Wh[n0 + 1];
        part = 0.f;
        #pragma unroll
        for (int mt = 0; mt < 2; ++mt) {
            part += tanhf(acc3[mt][0] + bq0) * wh0
                  + tanhf(acc3[mt][1] + bq1) * wh1
                  + tanhf(acc3[mt][2] + bq0) * wh0
                  + tanhf(acc3[mt][3] + bq1) * wh1;
        }
    }

    // ---- block reduce (fixed order) ----
    #pragma unroll
    for (int o = 16; o > 0; o >>= 1)
        part += __shfl_down_sync(0xffffffffu, part, o);
    if (lane == 0) sRed[wq] = part;
    __syncthreads();

    if (tid == 0) {
        float tot = 0.f;
        #pragma unroll
        for (int i = 0; i < 8; ++i) tot += sRed[i];
        g_partials[blockIdx.x] = tot;
        __threadfence();
        unsigned int c = atomicAdd(&g_count, 1u);
        sIsLast = (c == NBLK - 1u);
    }
    __syncthreads();

    // ---- last-done block: deterministic final reduction ----
    if (sIsLast) {
        volatile float* gp = g_partials;
        float v = gp[tid];                       // 256 partials, fixed order
        #pragma unroll
        for (int o = 16; o > 0; o >>= 1)
            v += __shfl_down_sync(0xffffffffu, v, o);
        if (lane == 0) sRed[wq] = v;
        __syncthreads();
        if (tid == 0) {
            float tfin = 0.f;
            #pragma unroll
            for (int i = 0; i < 8; ++i) tfin += sRed[i];
            out[0] = tfin + bh[0];
            g_count = 0;                           // self-reset for graph replay
        }
    }
}

extern "C" void kernel_launch(void* const* d_in, const int* in_sizes, int n_in,
                              void* d_out, int out_size)
{
    const float* S  = (const float*)d_in[0];
    const float* W1 = (const float*)d_in[1];
    const float* b1 = (const float*)d_in[2];
    const float* W2 = (const float*)d_in[3];
    const float* b2 = (const float*)d_in[4];
    const float* Wq = (const float*)d_in[5];
    const float* bq = (const float*)d_in[6];
    const float* Wh = (const float*)d_in[7];
    const float* bh = (const float*)d_in[8];
    float* out = (float*)d_out;

    const int dynsm = 65536;
    cudaFuncSetAttribute(fused_mlp_kernel,
                         cudaFuncAttributeMaxDynamicSharedMemorySize, dynsm);

    prep_W_kernel<<<104, 512>>>(W1, W2, Wq);
    fused_mlp_kernel<<<NBLK, NTHREADS, dynsm>>>(S, b1, b2, bq, Wh, bh, out);
}

// round 13
// speedup vs baseline: 4.3167x; 1.0499x over previous
#include <cuda_runtime.h>
#include <cuda_bf16.h>

// UnifiedQuantumRegressor — all-tensor fused MLP + reduction.
//
// Algebra (verified since R1): all edge weights are 1.0 -> mean_w == 1.0
// exactly -> attn == q_out; the O(N^2) fidelity stage is dead.
// out = (sum_i tanh(relu(relu(s_i@W1+b1)@W2+b2)@Wq+bq)) @ Wh + bh
//
// Stages 1+2+3: mma.sync m16n8k16 bf16, 3-pass split-compensated
//   (Ahi*Bhi + Ahi*Blo + Alo*Bhi, fp32 accum) -> ~2^-17 effective precision.
// R13: A-fragments stored interleaved {hi_klo,hi_khi,lo_klo,lo_khi} as one
//   uint4 -> 2 LDS.128 per m-tile (was 4 LDS.64): half the load instructions.
//   Depth-2 B prefetch (manual 2x-unrolled s-loop, two buffer sets).
//   __launch_bounds__(256,2) pins 2-CTA/SM residency.

#define NTHREADS 256
#define TM       32
#define NBLK     256          // 8192 / 32

// Packed B-fragments {bhi0,bhi1,blo0,blo1}:
__device__ uint4        g_W1pack[32 * 32 * 32];     // 512 KB
__device__ uint4        g_W2pack[16 * 32 * 32];     // 256 KB
__device__ uint4        g_WQpack[16 * 8 * 32];      //  64 KB
__device__ float        g_partials[NBLK];
__device__ unsigned int g_count;

static __device__ __forceinline__ unsigned pack_bf2(float a, float b) {
    __nv_bfloat162 h; h.x = __float2bfloat16(a); h.y = __float2bfloat16(b);
    return *(unsigned*)&h;
}
static __device__ __forceinline__ float bf_res(float x) {
    return x - __bfloat162float(__float2bfloat16(x));
}
static __device__ __forceinline__ void mma_bf16(float* d,
    unsigned a0, unsigned a1, unsigned a2, unsigned a3,
    unsigned b0, unsigned b1)
{
    asm volatile(
        "mma.sync.aligned.m16n8k16.row.col.f32.bf16.bf16.f32 "
        "{%0,%1,%2,%3}, {%4,%5,%6,%7}, {%8,%9}, {%0,%1,%2,%3};"
        : "+f"(d[0]), "+f"(d[1]), "+f"(d[2]), "+f"(d[3])
        : "r"(a0), "r"(a1), "r"(a2), "r"(a3), "r"(b0), "r"(b1));
}

// One s-step of 3-pass split MMAs for 2 m-tiles x 4 n8-blocks.
// A word layout: {hi_klo, hi_khi, lo_klo, lo_khi}.
static __device__ __forceinline__ void mma_group(
    float acc[2][4][4], const uint4* __restrict__ sbase, int a0,
    const uint4 B[4])
{
    #pragma unroll
    for (int mt = 0; mt < 2; ++mt) {
        const uint4 A0 = sbase[mt * 64 + a0];        // row g
        const uint4 A1 = sbase[mt * 64 + a0 + 32];   // row g+8
        #pragma unroll
        for (int nbi = 0; nbi < 4; ++nbi) {
            mma_bf16(acc[mt][nbi], A0.x, A1.x, A0.y, A1.y, B[nbi].x, B[nbi].y); // hi*hi
            mma_bf16(acc[mt][nbi], A0.x, A1.x, A0.y, A1.y, B[nbi].z, B[nbi].w); // hi*lo
            mma_bf16(acc[mt][nbi], A0.z, A1.z, A0.w, A1.w, B[nbi].x, B[nbi].y); // lo*hi
        }
    }
}

// ---- prep: split W1/W2/Wq into bf16 hi/lo, pack in B-fragment order ----
__global__ __launch_bounds__(512) void prep_W_kernel(
    const float* __restrict__ W1, const float* __restrict__ W2,
    const float* __restrict__ Wq)
{
    int idx = blockIdx.x * blockDim.x + threadIdx.x;     // 0 .. 53247
    const float* W;
    uint4* dst;
    int li, nb, s, ncols;
    if (idx < 32 * 32 * 32) {
        W = W1; dst = g_W1pack; li = idx;
        nb = (li >> 5) & 31; s = li >> 10; ncols = 256;
    } else if (idx < 48 * 32 * 32) {
        W = W2; dst = g_W2pack; li = idx - 32 * 32 * 32;
        nb = (li >> 5) & 31; s = li >> 10; ncols = 256;
    } else if (idx < 48 * 32 * 32 + 16 * 8 * 32) {
        W = Wq; dst = g_WQpack; li = idx - 48 * 32 * 32;
        nb = (li >> 5) & 7;  s = li >> 8;  ncols = 64;
    } else return;
    const int l = li & 31;
    const int g = l >> 2, t = l & 3;
    const int n  = nb * 8 + g;
    const int k0 = s * 16 + 2 * t;
    const float w00 = W[(k0    ) * ncols + n];
    const float w01 = W[(k0 + 1) * ncols + n];
    const float w10 = W[(k0 + 8) * ncols + n];
    const float w11 = W[(k0 + 9) * ncols + n];
    uint4 v;
    v.x = pack_bf2(w00, w01);
    v.y = pack_bf2(w10, w11);
    v.z = pack_bf2(bf_res(w00), bf_res(w01));
    v.w = pack_bf2(bf_res(w10), bf_res(w11));
    dst[li] = v;
}

__global__ __launch_bounds__(NTHREADS, 2) void fused_mlp_kernel(
    const float* __restrict__ S,   // [8192,512]
    const float* __restrict__ b1,  // [256]
    const float* __restrict__ b2,  // [256]
    const float* __restrict__ bq,  // [64]
    const float* __restrict__ Wh,  // [64]
    const float* __restrict__ bh,  // [1]
    float* __restrict__ out)
{
    extern __shared__ uint4 sm4[];     // 4096 uint4 = 64 KB
    // sA1: [32 s][32 r][4 t]  (S tile)              [0, 64K)
    // sA2: [16 s][32 r][4 t]  (enc1) overlays       [0, 32K)
    // sA3: [16 s][32 r][4 t]  (enc2) at             [32K, 64K)
    uint4* sA1 = sm4;
    uint4* sA2 = sm4;
    uint4* sA3 = sm4 + 2048;
    __shared__ float sRed[8];
    __shared__ int   sIsLast;

    const int tid  = threadIdx.x;
    const int wq   = tid >> 5;          // warp 0..7
    const int lane = tid & 31;
    const int g = lane >> 2, t = lane & 3;
    const int a0 = g * 4 + t;
    const int row0 = blockIdx.x * TM;

    // ---- stage S tile [32 x 512] into smem: interleaved hi/lo frag words ----
    {
        const int r  = tid >> 3;            // 0..31
        const int s0 = (tid & 7) * 4;       // 4 ksteps per thread
        const float* Srow = S + (size_t)(row0 + r) * 512;
        #pragma unroll
        for (int i = 0; i < 4; ++i) {
            const int s = s0 + i;
            const float4 x0 = *(const float4*)(Srow + s * 16);
            const float4 x1 = *(const float4*)(Srow + s * 16 + 4);
            const float4 x2 = *(const float4*)(Srow + s * 16 + 8);
            const float4 x3 = *(const float4*)(Srow + s * 16 + 12);
            const int base = s * 128 + r * 4;
            sA1[base + 0] = make_uint4(pack_bf2(x0.x, x0.y), pack_bf2(x2.x, x2.y),
                                       pack_bf2(bf_res(x0.x), bf_res(x0.y)),
                                       pack_bf2(bf_res(x2.x), bf_res(x2.y)));
            sA1[base + 1] = make_uint4(pack_bf2(x0.z, x0.w), pack_bf2(x2.z, x2.w),
                                       pack_bf2(bf_res(x0.z), bf_res(x0.w)),
                                       pack_bf2(bf_res(x2.z), bf_res(x2.w)));
            sA1[base + 2] = make_uint4(pack_bf2(x1.x, x1.y), pack_bf2(x3.x, x3.y),
                                       pack_bf2(bf_res(x1.x), bf_res(x1.y)),
                                       pack_bf2(bf_res(x3.x), bf_res(x3.y)));
            sA1[base + 3] = make_uint4(pack_bf2(x1.z, x1.w), pack_bf2(x3.z, x3.w),
                                       pack_bf2(bf_res(x1.z), bf_res(x1.w)),
                                       pack_bf2(bf_res(x3.z), bf_res(x3.w)));
        }
    }
    __syncthreads();

    // ============ stage 1: enc1 = relu(S @ W1 + b1) — tensor, depth-2 prefetch ============
    float acc1[2][4][4];
    {
        #pragma unroll
        for (int mt = 0; mt < 2; ++mt)
            #pragma unroll
            for (int nbi = 0; nbi < 4; ++nbi)
                #pragma unroll
                for (int j = 0; j < 4; ++j) acc1[mt][nbi][j] = 0.f;

        const uint4* bb = g_W1pack + wq * 4 * 32 + lane;
        uint4 B0[4], B1[4];
        #pragma unroll
        for (int nbi = 0; nbi < 4; ++nbi) B0[nbi] = bb[nbi * 32];
        #pragma unroll
        for (int nbi = 0; nbi < 4; ++nbi) B1[nbi] = bb[1024 + nbi * 32];

        #pragma unroll 1
        for (int s = 0; s < 32; s += 2) {
            {   // sub-iter s: consume B0, prefetch s+2 -> B0
                const uint4* bp = bb + ((s + 2 < 32) ? (s + 2) : 31) * 1024;
                uint4 Bp[4];
                #pragma unroll
                for (int nbi = 0; nbi < 4; ++nbi) Bp[nbi] = bp[nbi * 32];
                mma_group(acc1, sA1 + s * 128, a0, B0);
                #pragma unroll
                for (int nbi = 0; nbi < 4; ++nbi) B0[nbi] = Bp[nbi];
            }
            {   // sub-iter s+1: consume B1, prefetch s+3 -> B1
                const uint4* bp = bb + ((s + 3 < 32) ? (s + 3) : 31) * 1024;
                uint4 Bp[4];
                #pragma unroll
                for (int nbi = 0; nbi < 4; ++nbi) Bp[nbi] = bp[nbi * 32];
                mma_group(acc1, sA1 + (s + 1) * 128, a0, B1);
                #pragma unroll
                for (int nbi = 0; nbi < 4; ++nbi) B1[nbi] = Bp[nbi];
            }
        }
    }
    __syncthreads();                       // sA1 reads done; region reusable

    // epilogue 1: bias+relu -> enc1 as interleaved hi/lo A-words (sA2)
    {
        #pragma unroll
        for (int nbi = 0; nbi < 4; ++nbi) {
            const int n0 = wq * 32 + nbi * 8 + 2 * t;
            const float bb0 = b1[n0], bb1 = b1[n0 + 1];
            const int s2 = 2 * wq + (nbi >> 1);
            const int half = nbi & 1;
            #pragma unroll
            for (int mt = 0; mt < 2; ++mt) {
                const int mlo = mt * 16 + g;
                const float vl0 = fmaxf(acc1[mt][nbi][0] + bb0, 0.f);
                const float vl1 = fmaxf(acc1[mt][nbi][1] + bb1, 0.f);
                const float vh0 = fmaxf(acc1[mt][nbi][2] + bb0, 0.f);
                const float vh1 = fmaxf(acc1[mt][nbi][3] + bb1, 0.f);
                unsigned* plo = (unsigned*)&sA2[s2 * 128 + mlo * 4 + t];
                unsigned* phi = plo + 32 * 4;                  // row +8
                plo[half]     = pack_bf2(vl0, vl1);
                plo[2 + half] = pack_bf2(bf_res(vl0), bf_res(vl1));
                phi[half]     = pack_bf2(vh0, vh1);
                phi[2 + half] = pack_bf2(bf_res(vh0), bf_res(vh1));
            }
        }
    }
    __syncthreads();

    // ============ stage 2: enc2 = relu(enc1 @ W2 + b2) — tensor, depth-2 prefetch ============
    float acc2[2][4][4];
    {
        #pragma unroll
        for (int mt = 0; mt < 2; ++mt)
            #pragma unroll
            for (int nbi = 0; nbi < 4; ++nbi)
                #pragma unroll
                for (int j = 0; j < 4; ++j) acc2[mt][nbi][j] = 0.f;

        const uint4* bb = g_W2pack + wq * 4 * 32 + lane;
        uint4 B0[4], B1[4];
        #pragma unroll
        for (int nbi = 0; nbi < 4; ++nbi) B0[nbi] = bb[nbi * 32];
        #pragma unroll
        for (int nbi = 0; nbi < 4; ++nbi) B1[nbi] = bb[1024 + nbi * 32];

        #pragma unroll 1
        for (int s = 0; s < 16; s += 2) {
            {
                const uint4* bp = bb + ((s + 2 < 16) ? (s + 2) : 15) * 1024;
                uint4 Bp[4];
                #pragma unroll
                for (int nbi = 0; nbi < 4; ++nbi) Bp[nbi] = bp[nbi * 32];
                mma_group(acc2, sA2 + s * 128, a0, B0);
                #pragma unroll
                for (int nbi = 0; nbi < 4; ++nbi) B0[nbi] = Bp[nbi];
            }
            {
                const uint4* bp = bb + ((s + 3 < 16) ? (s + 3) : 15) * 1024;
                uint4 Bp[4];
                #pragma unroll
                for (int nbi = 0; nbi < 4; ++nbi) Bp[nbi] = bp[nbi * 32];
                mma_group(acc2, sA2 + (s + 1) * 128, a0, B1);
                #pragma unroll
                for (int nbi = 0; nbi < 4; ++nbi) B1[nbi] = Bp[nbi];
            }
        }
    }
    // epilogue 2: bias+relu -> enc2 A-words into sA3 (distinct region; no
    // readers until the next __syncthreads, writes are thread-private data).
    {
        #pragma unroll
        for (int nbi = 0; nbi < 4; ++nbi) {
            const int n0 = wq * 32 + nbi * 8 + 2 * t;
            const float bb0 = b2[n0], bb1 = b2[n0 + 1];
            const int s2 = 2 * wq + (nbi >> 1);
            const int half = nbi & 1;
            #pragma unroll
            for (int mt = 0; mt < 2; ++mt) {
                const int mlo = mt * 16 + g;
                const float vl0 = fmaxf(acc2[mt][nbi][0] + bb0, 0.f);
                const float vl1 = fmaxf(acc2[mt][nbi][1] + bb1, 0.f);
                const float vh0 = fmaxf(acc2[mt][nbi][2] + bb0, 0.f);
                const float vh1 = fmaxf(acc2[mt][nbi][3] + bb1, 0.f);
                unsigned* plo = (unsigned*)&sA3[s2 * 128 + mlo * 4 + t];
                unsigned* phi = plo + 32 * 4;
                plo[half]     = pack_bf2(vl0, vl1);
                plo[2 + half] = pack_bf2(bf_res(vl0), bf_res(vl1));
                phi[half]     = pack_bf2(vh0, vh1);
                phi[2 + half] = pack_bf2(bf_res(vh0), bf_res(vh1));
            }
        }
    }
    __syncthreads();

    // ====== stage 3: qpre = enc2 @ Wq — tensor; warp wq owns n8-block wq ======
    float acc3[2][4];
    {
        #pragma unroll
        for (int mt = 0; mt < 2; ++mt)
            #pragma unroll
            for (int j = 0; j < 4; ++j) acc3[mt][j] = 0.f;

        const uint4* qb = g_WQpack + wq * 32 + lane;    // + s*256
        uint4 C0 = qb[0];
        uint4 C1 = qb[256];

        #pragma unroll 1
        for (int s = 0; s < 16; s += 2) {
            {
                const uint4 Cp = qb[((s + 2 < 16) ? (s + 2) : 15) * 256];
                #pragma unroll
                for (int mt = 0; mt < 2; ++mt) {
                    const uint4 A0 = sA3[s * 128 + mt * 64 + a0];
                    const uint4 A1 = sA3[s * 128 + mt * 64 + a0 + 32];
                    mma_bf16(acc3[mt], A0.x, A1.x, A0.y, A1.y, C0.x, C0.y);
                    mma_bf16(acc3[mt], A0.x, A1.x, A0.y, A1.y, C0.z, C0.w);
                    mma_bf16(acc3[mt], A0.z, A1.z, A0.w, A1.w, C0.x, C0.y);
                }
                C0 = Cp;
            }
            {
                const uint4 Cp = qb[((s + 3 < 16) ? (s + 3) : 15) * 256];
                #pragma unroll
                for (int mt = 0; mt < 2; ++mt) {
                    const uint4 A0 = sA3[(s + 1) * 128 + mt * 64 + a0];
                    const uint4 A1 = sA3[(s + 1) * 128 + mt * 64 + a0 + 32];
                    mma_bf16(acc3[mt], A0.x, A1.x, A0.y, A1.y, C1.x, C1.y);
                    mma_bf16(acc3[mt], A0.x, A1.x, A0.y, A1.y, C1.z, C1.w);
                    mma_bf16(acc3[mt], A0.z, A1.z, A0.w, A1.w, C1.x, C1.y);
                }
                C1 = Cp;
            }
        }
    }

    // epilogue 3: q = tanh(qpre + bq); part = q . Wh
    float part;
    {
        const int n0 = wq * 8 + 2 * t;
        const float bq0 = bq[n0], bq1 = bq[n0 + 1];
        const float wh0 = Wh[n0], wh1 = Wh[n0 + 1];
        part = 0.f;
        #pragma unroll
        for (int mt = 0; mt < 2; ++mt) {
            part += tanhf(acc3[mt][0] + bq0) * wh0
                  + tanhf(acc3[mt][1] + bq1) * wh1
                  + tanhf(acc3[mt][2] + bq0) * wh0
                  + tanhf(acc3[mt][3] + bq1) * wh1;
        }
    }

    // ---- block reduce (fixed order) ----
    #pragma unroll
    for (int o = 16; o > 0; o >>= 1)
        part += __shfl_down_sync(0xffffffffu, part, o);
    if (lane == 0) sRed[wq] = part;
    __syncthreads();

    if (tid == 0) {
        float tot = 0.f;
        #pragma unroll
        for (int i = 0; i < 8; ++i) tot += sRed[i];
        g_partials[blockIdx.x] = tot;
        __threadfence();
        unsigned int c = atomicAdd(&g_count, 1u);
        sIsLast = (c == NBLK - 1u);
    }
    __syncthreads();

    // ---- last-done block: deterministic final reduction ----
    if (sIsLast) {
        volatile float* gp = g_partials;
        float v = gp[tid];                       // 256 partials, fixed order
        #pragma unroll
        for (int o = 16; o > 0; o >>= 1)
            v += __shfl_down_sync(0xffffffffu, v, o);
        if (lane == 0) sRed[wq] = v;
        __syncthreads();
        if (tid == 0) {
            float tfin = 0.f;
            #pragma unroll
            for (int i = 0; i < 8; ++i) tfin += sRed[i];
            out[0] = tfin + bh[0];
            g_count = 0;                           // self-reset for graph replay
        }
    }
}

extern "C" void kernel_launch(void* const* d_in, const int* in_sizes, int n_in,
                              void* d_out, int out_size)
{
    const float* S  = (const float*)d_in[0];
    const float* W1 = (const float*)d_in[1];
    const float* b1 = (const float*)d_in[2];
    const float* W2 = (const float*)d_in[3];
    const float* b2 = (const float*)d_in[4];
    const float* Wq = (const float*)d_in[5];
    const float* bq = (const float*)d_in[6];
    const float* Wh = (const float*)d_in[7];
    const float* bh = (const float*)d_in[8];
    float* out = (float*)d_out;

    const int dynsm = 65536;
    cudaFuncSetAttribute(fused_mlp_kernel,
                         cudaFuncAttributeMaxDynamicSharedMemorySize, dynsm);

    prep_W_kernel<<<104, 512>>>(W1, W2, Wq);
    fused_mlp_kernel<<<NBLK, NTHREADS, dynsm>>>(S, b1, b2, bq, Wh, bh, out);
}